// round 7
// baseline (speedup 1.0000x reference)
#include <cuda_runtime.h>
#include <cuda_bf16.h>
#include <math.h>
#include <stdint.h>

// Problem constants
#define BB 2
#define TT 2048
#define EE 1024
#define HH 16
#define KVH 4
#define HD 64
#define GG 4           // H / KVH
#define MM (BB*TT)     // 4096 rows

// ---------------------------------------------------------------------------
// Device scratch (allocation-free rule: __device__ globals)
// ---------------------------------------------------------------------------
__device__ float g_q[MM*EE];
__device__ float g_k[MM*KVH*HD];
__device__ float g_v[MM*KVH*HD];

__device__ __nv_bfloat16 g_x_hi[MM*EE],      g_x_lo[MM*EE];
__device__ __nv_bfloat16 g_y_hi[MM*EE],      g_y_lo[MM*EE];
__device__ __nv_bfloat16 g_wq_hi[EE*EE],     g_wq_lo[EE*EE];
__device__ __nv_bfloat16 g_wk_hi[KVH*HD*EE], g_wk_lo[KVH*HD*EE];
__device__ __nv_bfloat16 g_wv_hi[KVH*HD*EE], g_wv_lo[KVH*HD*EE];
__device__ __nv_bfloat16 g_wo_hi[EE*EE],     g_wo_lo[EE*EE];

__device__ __nv_bfloat16 g_qh[MM*EE],        g_ql[MM*EE];
__device__ __nv_bfloat16 g_kh[MM*KVH*HD],    g_kl[MM*KVH*HD];
__device__ __nv_bfloat16 g_vh[MM*KVH*HD],    g_vl[MM*KVH*HD];

// ---------------------------------------------------------------------------
// PTX helpers
// ---------------------------------------------------------------------------
__device__ __forceinline__ uint32_t smem_u32(const void* p) {
    uint32_t a;
    asm("{ .reg .u64 t; cvta.to.shared.u64 t, %1; cvt.u32.u64 %0, t; }"
        : "=r"(a) : "l"(p));
    return a;
}

#define LDSM4(r, addr) \
    asm volatile("ldmatrix.sync.aligned.m8n8.x4.shared.b16 {%0,%1,%2,%3}, [%4];" \
        : "=r"((r)[0]), "=r"((r)[1]), "=r"((r)[2]), "=r"((r)[3]) : "r"(addr))

#define LDSM4T(r, addr) \
    asm volatile("ldmatrix.sync.aligned.m8n8.x4.trans.shared.b16 {%0,%1,%2,%3}, [%4];" \
        : "=r"((r)[0]), "=r"((r)[1]), "=r"((r)[2]), "=r"((r)[3]) : "r"(addr))

#define MMA_BF16(d, a, b) \
    asm volatile("mma.sync.aligned.m16n8k16.row.col.f32.bf16.bf16.f32 " \
        "{%0,%1,%2,%3}, {%4,%5,%6,%7}, {%8,%9}, {%0,%1,%2,%3};" \
        : "+f"((d)[0]), "+f"((d)[1]), "+f"((d)[2]), "+f"((d)[3]) \
        : "r"((a)[0]), "r"((a)[1]), "r"((a)[2]), "r"((a)[3]), \
          "r"((b)[0]), "r"((b)[1]))

#define CP_ASYNC16(dst, src) \
    asm volatile("cp.async.cg.shared.global [%0], [%1], 16;" \
        :: "r"(dst), "l"(src))
#define CP_COMMIT() asm volatile("cp.async.commit_group;" ::: "memory")
#define CP_WAIT0()  asm volatile("cp.async.wait_group 0;" ::: "memory")
#define CP_WAIT1()  asm volatile("cp.async.wait_group 1;" ::: "memory")

__device__ __forceinline__ uint32_t pack_bf16(float lo, float hi) {
    __nv_bfloat162 t = __float22bfloat162_rn(make_float2(lo, hi));
    return *reinterpret_cast<uint32_t*>(&t);
}

// ---------------------------------------------------------------------------
// Batched split
// ---------------------------------------------------------------------------
struct SplitArgs {
    const float*   in[5];
    __nv_bfloat16* hi[5];
    __nv_bfloat16* lo[5];
    int            n4[5];
};

__device__ __forceinline__ void split_one(const float* __restrict__ in,
                                          __nv_bfloat16* __restrict__ hi,
                                          __nv_bfloat16* __restrict__ lo, int i)
{
    float4 v = reinterpret_cast<const float4*>(in)[i];
    float f[4] = {v.x, v.y, v.z, v.w};
    __nv_bfloat16 h0 = __float2bfloat16(f[0]);
    __nv_bfloat16 h1 = __float2bfloat16(f[1]);
    __nv_bfloat16 h2 = __float2bfloat16(f[2]);
    __nv_bfloat16 h3 = __float2bfloat16(f[3]);
    __nv_bfloat16 l0 = __float2bfloat16(f[0] - __bfloat162float(h0));
    __nv_bfloat16 l1 = __float2bfloat16(f[1] - __bfloat162float(h1));
    __nv_bfloat16 l2 = __float2bfloat16(f[2] - __bfloat162float(h2));
    __nv_bfloat16 l3 = __float2bfloat16(f[3] - __bfloat162float(h3));
    uint32_t ph0 = (uint32_t)__bfloat16_as_ushort(h0) | ((uint32_t)__bfloat16_as_ushort(h1) << 16);
    uint32_t ph1 = (uint32_t)__bfloat16_as_ushort(h2) | ((uint32_t)__bfloat16_as_ushort(h3) << 16);
    uint32_t pl0 = (uint32_t)__bfloat16_as_ushort(l0) | ((uint32_t)__bfloat16_as_ushort(l1) << 16);
    uint32_t pl1 = (uint32_t)__bfloat16_as_ushort(l2) | ((uint32_t)__bfloat16_as_ushort(l3) << 16);
    reinterpret_cast<uint2*>(hi)[i] = make_uint2(ph0, ph1);
    reinterpret_cast<uint2*>(lo)[i] = make_uint2(pl0, pl1);
}

__global__ void split_all(SplitArgs a)
{
    int seg = blockIdx.y;
    int i   = blockIdx.x * blockDim.x + threadIdx.x;
    if (i >= a.n4[seg]) return;
    split_one(a.in[seg], a.hi[seg], a.lo[seg], i);
}

// ---------------------------------------------------------------------------
// rope_all: y=0 q rope+split, y=1 k rope+split, y=2 v plain split
// ---------------------------------------------------------------------------
__global__ void rope_all(const float* __restrict__ q,
                         const float* __restrict__ k,
                         const float* __restrict__ v,
                         const float* __restrict__ c,
                         const float* __restrict__ s,
                         __nv_bfloat16* __restrict__ qh, __nv_bfloat16* __restrict__ ql,
                         __nv_bfloat16* __restrict__ kh, __nv_bfloat16* __restrict__ kl,
                         __nv_bfloat16* __restrict__ vh, __nv_bfloat16* __restrict__ vl)
{
    int seg = blockIdx.y;
    int idx = blockIdx.x * blockDim.x + threadIdx.x;
    if (seg == 2) {
        int n4 = MM * KVH * HD / 4;
        if (idx >= n4) return;
        split_one(v, vh, vl, idx);
        return;
    }
    const float* x = (seg == 0) ? q : k;
    __nv_bfloat16* hi = (seg == 0) ? qh : kh;
    __nv_bfloat16* lo = (seg == 0) ? ql : kl;
    int heads = (seg == 0) ? HH : KVH;
    int n = BB * TT * heads * 32;
    if (idx >= n) return;

    int d  = idx & 31;
    int r  = idx >> 5;
    int h  = r % heads;
    int bt = r / heads;

    const float* p  = x + ((size_t)bt * heads + h) * 64;
    const float* cp = c + (size_t)bt * 64;
    const float* sp = s + (size_t)bt * 64;

    float x1 = p[d];
    float x2 = p[d + 32];
    float y1 = x1 * cp[d]      - x2 * sp[d];
    float y2 = x2 * cp[d + 32] + x1 * sp[d + 32];

    size_t o = ((size_t)bt * heads + h) * 64;
    __nv_bfloat16 h1 = __float2bfloat16(y1);
    __nv_bfloat16 h2 = __float2bfloat16(y2);
    hi[o + d]      = h1;
    hi[o + d + 32] = h2;
    lo[o + d]      = __float2bfloat16(y1 - __bfloat162float(h1));
    lo[o + d + 32] = __float2bfloat16(y2 - __bfloat162float(h2));
}

// ---------------------------------------------------------------------------
// mma.sync GEMM body: C[M,N] = A[M,K] * W[N,K]^T, bf16x2 split (hh+hl+lh)
// ---------------------------------------------------------------------------
#define TILE_BYTES   10240
#define BUF_BYTES    (4*TILE_BYTES)
#define GEMM_SMEM    (2*BUF_BYTES)

__device__ __forceinline__ void issue_tile(
    uint32_t sbuf,
    const __nv_bfloat16* __restrict__ Ahi, const __nv_bfloat16* __restrict__ Alo,
    const __nv_bfloat16* __restrict__ Bhi, const __nv_bfloat16* __restrict__ Blo,
    int m0, int n0, int k0, int K, int tid)
{
    #pragma unroll
    for (int it = 0; it < 2; it++) {
        int idx = tid + it * 256;
        int r   = idx >> 2;
        int c8  = idx & 3;
        uint32_t so = (uint32_t)(r * 80 + c8 * 16);
        size_t ga = (size_t)(m0 + r) * K + k0 + c8 * 8;
        size_t gb = (size_t)(n0 + r) * K + k0 + c8 * 8;
        CP_ASYNC16(sbuf + so,                 (const char*)(Ahi + ga));
        CP_ASYNC16(sbuf + TILE_BYTES + so,    (const char*)(Alo + ga));
        CP_ASYNC16(sbuf + 2*TILE_BYTES + so,  (const char*)(Bhi + gb));
        CP_ASYNC16(sbuf + 3*TILE_BYTES + so,  (const char*)(Blo + gb));
    }
}

__device__ __forceinline__ void gemm_body(
    uint32_t sbase,
    const __nv_bfloat16* __restrict__ Ahi, const __nv_bfloat16* __restrict__ Alo,
    const __nv_bfloat16* __restrict__ Bhi, const __nv_bfloat16* __restrict__ Blo,
    float* __restrict__ C, int M, int N, int K, int m0, int n0)
{
    const int tid  = threadIdx.x;
    const int lane = tid & 31;
    const int wid  = tid >> 5;
    const int wm   = wid >> 2;
    const int wn   = wid & 3;

    float acc[4][4][4];
    #pragma unroll
    for (int i = 0; i < 4; i++)
        #pragma unroll
        for (int j = 0; j < 4; j++)
            #pragma unroll
            for (int r = 0; r < 4; r++) acc[i][j][r] = 0.f;

    const uint32_t a_row  = (uint32_t)(wm * 64 + (lane & 15));
    const uint32_t a_k8   = (uint32_t)(lane >> 4);
    const uint32_t b_row  = (uint32_t)(wn * 32 + (lane & 7) + ((lane >> 4) << 3));
    const uint32_t b_k8   = (uint32_t)((lane >> 3) & 1);

    const int NK = K / 32;
    issue_tile(sbase, Ahi, Alo, Bhi, Blo, m0, n0, 0, K, tid);
    CP_COMMIT();

    for (int kt = 0; kt < NK; kt++) {
        CP_WAIT0();
        __syncthreads();
        if (kt + 1 < NK) {
            issue_tile(sbase + (uint32_t)((kt + 1) & 1) * BUF_BYTES,
                       Ahi, Alo, Bhi, Blo, m0, n0, (kt + 1) * 32, K, tid);
            CP_COMMIT();
        }
        const uint32_t buf = sbase + (uint32_t)(kt & 1) * BUF_BYTES;

        #pragma unroll
        for (int ks = 0; ks < 2; ks++) {
            uint32_t ah[4][4], al[4][4], bh[2][4], bl[2][4];
            #pragma unroll
            for (int mb = 0; mb < 4; mb++) {
                uint32_t addr = buf + (a_row + mb * 16) * 80
                                    + (ks * 2 + a_k8) * 16;
                LDSM4(ah[mb], addr);
                LDSM4(al[mb], addr + TILE_BYTES);
            }
            #pragma unroll
            for (int nb = 0; nb < 2; nb++) {
                uint32_t addr = buf + 2*TILE_BYTES
                                    + (b_row + nb * 16) * 80
                                    + (ks * 2 + b_k8) * 16;
                LDSM4(bh[nb], addr);
                LDSM4(bl[nb], addr + TILE_BYTES);
            }
            #pragma unroll
            for (int mb = 0; mb < 4; mb++) {
                #pragma unroll
                for (int n8 = 0; n8 < 4; n8++) {
                    uint32_t* Bh = &bh[n8 >> 1][(n8 & 1) * 2];
                    uint32_t* Bl = &bl[n8 >> 1][(n8 & 1) * 2];
                    MMA_BF16(acc[mb][n8], ah[mb], Bh);
                    MMA_BF16(acc[mb][n8], ah[mb], Bl);
                    MMA_BF16(acc[mb][n8], al[mb], Bh);
                }
            }
        }
    }

    #pragma unroll
    for (int mb = 0; mb < 4; mb++) {
        int row = m0 + wm * 64 + mb * 16 + (lane >> 2);
        #pragma unroll
        for (int n8 = 0; n8 < 4; n8++) {
            int col = n0 + wn * 32 + n8 * 8 + (lane & 3) * 2;
            *reinterpret_cast<float2*>(&C[(size_t)row * N + col]) =
                make_float2(acc[mb][n8][0], acc[mb][n8][1]);
            *reinterpret_cast<float2*>(&C[(size_t)(row + 8) * N + col]) =
                make_float2(acc[mb][n8][2], acc[mb][n8][3]);
        }
    }
}

__global__ __launch_bounds__(256) void gemm_mma(
    const __nv_bfloat16* __restrict__ Ahi, const __nv_bfloat16* __restrict__ Alo,
    const __nv_bfloat16* __restrict__ Bhi, const __nv_bfloat16* __restrict__ Blo,
    float* __restrict__ C, int M, int N, int K)
{
    extern __shared__ char sm[];
    gemm_body(smem_u32(sm), Ahi, Alo, Bhi, Blo, C, M, N, K,
              blockIdx.y * 128, blockIdx.x * 128);
}

// combined Q/K/V projections
__global__ __launch_bounds__(256) void gemm_mma_qkv(
    const __nv_bfloat16* __restrict__ Ahi, const __nv_bfloat16* __restrict__ Alo,
    const __nv_bfloat16* __restrict__ Wqh, const __nv_bfloat16* __restrict__ Wql,
    const __nv_bfloat16* __restrict__ Wkh, const __nv_bfloat16* __restrict__ Wkl,
    const __nv_bfloat16* __restrict__ Wvh, const __nv_bfloat16* __restrict__ Wvl,
    float* __restrict__ Cq, float* __restrict__ Ck, float* __restrict__ Cv)
{
    extern __shared__ char sm[];
    int bx = blockIdx.x;
    const __nv_bfloat16 *Bh, *Bl;
    float* C;
    int N, n0;
    if (bx < 8)       { Bh = Wqh; Bl = Wql; C = Cq; N = EE;       n0 = bx * 128; }
    else if (bx < 10) { Bh = Wkh; Bl = Wkl; C = Ck; N = KVH * HD; n0 = (bx - 8) * 128; }
    else              { Bh = Wvh; Bl = Wvl; C = Cv; N = KVH * HD; n0 = (bx - 10) * 128; }
    gemm_body(smem_u32(sm), Ahi, Alo, Bh, Bl, C, MM, N, EE,
              blockIdx.y * 128, n0);
}

// ---------------------------------------------------------------------------
// Flash attention, 1 head per CTA, bf16 hi/lo split, BM=BN=64.
// 128 threads = 4 warps; big-first scheduling; base-2 softmax; diag MMA skip.
// Epilogue emits yh/yl bf16 directly (no separate split kernel).
// ---------------------------------------------------------------------------
#define FROW      144
#define FARR      (64*FROW)            // 9216
#define SM_QH     0
#define SM_QL     FARR
#define SM_KV0    (2*FARR)
#define KVBUF     (4*FARR)
#define OFF_KH    0
#define OFF_KL    FARR
#define OFF_VH    (2*FARR)
#define OFF_VL    (3*FARR)
#define FLASH_SMEM (10*FARR)           // 92160  (2 CTAs/SM: 184320 < 228K)

#define SCALE_L2E 0.180336879f         // 0.125 * log2(e)

__device__ __forceinline__ void flash_load_kv(
    uint32_t kb,
    const __nv_bfloat16* __restrict__ kh, const __nv_bfloat16* __restrict__ kl,
    const __nv_bfloat16* __restrict__ vh, const __nv_bfloat16* __restrict__ vl,
    int b, int kt, int kvh, int tid)
{
    #pragma unroll
    for (int it = 0; it < 4; it++) {
        int idx = tid + it * 128;
        int r   = idx >> 3;
        int c   = idx & 7;
        size_t g = (size_t)(b * TT + kt * 64 + r) * (KVH * HD) + kvh * 64 + c * 8;
        uint32_t so = (uint32_t)(r * FROW + c * 16);
        CP_ASYNC16(kb + OFF_KH + so, (const char*)(kh + g));
        CP_ASYNC16(kb + OFF_KL + so, (const char*)(kl + g));
        CP_ASYNC16(kb + OFF_VH + so, (const char*)(vh + g));
        CP_ASYNC16(kb + OFF_VL + so, (const char*)(vl + g));
    }
}

__global__ __launch_bounds__(128, 2) void flash_mma(
    const __nv_bfloat16* __restrict__ qh, const __nv_bfloat16* __restrict__ ql,
    const __nv_bfloat16* __restrict__ kh, const __nv_bfloat16* __restrict__ kl,
    const __nv_bfloat16* __restrict__ vh, const __nv_bfloat16* __restrict__ vl,
    __nv_bfloat16* __restrict__ yh, __nv_bfloat16* __restrict__ yl)
{
    extern __shared__ char sm[];
    const uint32_t sb = smem_u32(sm);
    const int tid  = threadIdx.x;
    const int lane = tid & 31;
    const int wid  = tid >> 5;
    const int qt   = (int)(gridDim.x - 1 - blockIdx.x);   // big tiles first
    const int h    = blockIdx.y;
    const int b    = blockIdx.z;
    const int kvh  = h / GG;

    // prologue: Q (hi+lo) + KV tile 0
    #pragma unroll
    for (int it = 0; it < 4; it++) {
        int idx = tid + it * 128;
        int r   = idx >> 3;
        int c   = idx & 7;
        size_t g = (size_t)(b * TT + qt * 64 + r) * EE + h * 64 + c * 8;
        uint32_t so = (uint32_t)(r * FROW + c * 16);
        CP_ASYNC16(sb + SM_QH + so, (const char*)(qh + g));
        CP_ASYNC16(sb + SM_QL + so, (const char*)(ql + g));
    }
    CP_COMMIT();
    flash_load_kv(sb + SM_KV0, kh, kl, vh, vl, b, 0, kvh, tid);
    CP_COMMIT();

    CP_WAIT1();
    __syncthreads();

    // Q A-fragments resident
    uint32_t qfh[4][4], qfl[4][4];
    {
        const uint32_t a_row = (uint32_t)(wid * 16 + (lane & 15));
        const uint32_t a_k8  = (uint32_t)(lane >> 4);
        #pragma unroll
        for (int ks = 0; ks < 4; ks++) {
            uint32_t addr = sb + SM_QH + a_row * FROW + (ks * 2 + a_k8) * 16;
            LDSM4(qfh[ks], addr);
            LDSM4(qfl[ks], addr + FARR);
        }
    }

    const uint32_t kb_row = (uint32_t)((lane & 7) + ((lane >> 4) << 3));
    const uint32_t kb_k8  = (uint32_t)((lane >> 3) & 1);
    const uint32_t vb_row = (uint32_t)((lane & 7) + (((lane >> 3) & 1) << 3));
    const uint32_t vb_col = (uint32_t)((lane >> 4) << 3);

    float oacc[8][4];
    #pragma unroll
    for (int nb = 0; nb < 8; nb++)
        #pragma unroll
        for (int j = 0; j < 4; j++) oacc[nb][j] = 0.f;
    float m0 = -INFINITY, m1 = -INFINITY, l0 = 0.f, l1 = 0.f;

    int cur = 0;
    for (int kt = 0; kt <= qt; kt++) {
        if (kt + 1 <= qt) {
            flash_load_kv(sb + SM_KV0 + (uint32_t)(cur ^ 1) * KVBUF,
                          kh, kl, vh, vl, b, kt + 1, kvh, tid);
            CP_COMMIT();
            CP_WAIT1();
        } else {
            CP_WAIT0();
        }
        __syncthreads();
        const uint32_t kvb = sb + SM_KV0 + (uint32_t)cur * KVBUF;
        const bool diag = (kt == qt);
        const int nbmax = diag ? wid : 3;   // skip fully-masked key blocks

        // ---- S = Q K^T (3-term split) ----
        float sacc[8][4];
        #pragma unroll
        for (int nb = 0; nb < 8; nb++)
            #pragma unroll
            for (int j = 0; j < 4; j++) sacc[nb][j] = 0.f;

        #pragma unroll
        for (int ks = 0; ks < 4; ks++) {
            for (int nb = 0; nb <= nbmax; nb++) {
                uint32_t addr = kvb + OFF_KH + (kb_row + nb * 16) * FROW
                                            + (ks * 2 + kb_k8) * 16;
                uint32_t bh[4], bl[4];
                LDSM4(bh, addr);
                LDSM4(bl, addr + FARR);
                MMA_BF16(sacc[2*nb],   qfh[ks], bh);
                MMA_BF16(sacc[2*nb],   qfh[ks], bl);
                MMA_BF16(sacc[2*nb],   qfl[ks], bh);
                MMA_BF16(sacc[2*nb+1], qfh[ks], bh + 2);
                MMA_BF16(sacc[2*nb+1], qfh[ks], bl + 2);
                MMA_BF16(sacc[2*nb+1], qfl[ks], bh + 2);
            }
        }

        // ---- scale (base-2) + causal mask ----
        #pragma unroll
        for (int nb = 0; nb < 8; nb++)
            #pragma unroll
            for (int j = 0; j < 4; j++) sacc[nb][j] *= SCALE_L2E;
        if (diag) {
            #pragma unroll
            for (int nb = 0; nb < 8; nb++)
                #pragma unroll
                for (int j = 0; j < 4; j++) {
                    int n_loc = nb * 8 + 2 * (lane & 3) + (j & 1);
                    int m_loc = wid * 16 + (lane >> 2) + ((j >> 1) << 3);
                    if (n_loc > m_loc || (nb >> 1) > nbmax)
                        sacc[nb][j] = -1e30f;
                }
        }

        // ---- online softmax (base-2) ----
        float mx0 = -INFINITY, mx1 = -INFINITY;
        #pragma unroll
        for (int nb = 0; nb < 8; nb++) {
            mx0 = fmaxf(mx0, fmaxf(sacc[nb][0], sacc[nb][1]));
            mx1 = fmaxf(mx1, fmaxf(sacc[nb][2], sacc[nb][3]));
        }
        mx0 = fmaxf(mx0, __shfl_xor_sync(0xffffffffu, mx0, 1));
        mx0 = fmaxf(mx0, __shfl_xor_sync(0xffffffffu, mx0, 2));
        mx1 = fmaxf(mx1, __shfl_xor_sync(0xffffffffu, mx1, 1));
        mx1 = fmaxf(mx1, __shfl_xor_sync(0xffffffffu, mx1, 2));

        float mn0 = fmaxf(m0, mx0), mn1 = fmaxf(m1, mx1);
        float al0 = exp2f(m0 - mn0), al1 = exp2f(m1 - mn1);
        m0 = mn0; m1 = mn1;

        float sum0 = 0.f, sum1 = 0.f;
        #pragma unroll
        for (int nb = 0; nb < 8; nb++) {
            sacc[nb][0] = exp2f(sacc[nb][0] - mn0);
            sacc[nb][1] = exp2f(sacc[nb][1] - mn0);
            sacc[nb][2] = exp2f(sacc[nb][2] - mn1);
            sacc[nb][3] = exp2f(sacc[nb][3] - mn1);
            sum0 += sacc[nb][0] + sacc[nb][1];
            sum1 += sacc[nb][2] + sacc[nb][3];
        }
        sum0 += __shfl_xor_sync(0xffffffffu, sum0, 1);
        sum0 += __shfl_xor_sync(0xffffffffu, sum0, 2);
        sum1 += __shfl_xor_sync(0xffffffffu, sum1, 1);
        sum1 += __shfl_xor_sync(0xffffffffu, sum1, 2);
        l0 = l0 * al0 + sum0;
        l1 = l1 * al1 + sum1;

        #pragma unroll
        for (int nb = 0; nb < 8; nb++) {
            oacc[nb][0] *= al0; oacc[nb][1] *= al0;
            oacc[nb][2] *= al1; oacc[nb][3] *= al1;
        }

        // ---- pack P hi/lo A-fragments ----
        uint32_t pfh[4][4], pfl[4][4];
        #pragma unroll
        for (int j16 = 0; j16 < 4; j16++) {
            float* c0 = sacc[2*j16];
            float* c1 = sacc[2*j16 + 1];
            #pragma unroll
            for (int a = 0; a < 4; a++) {
                float v0 = (a < 2) ? c0[(a & 1) * 2]     : c1[(a & 1) * 2];
                float v1 = (a < 2) ? c0[(a & 1) * 2 + 1] : c1[(a & 1) * 2 + 1];
                __nv_bfloat16 t0 = __float2bfloat16(v0);
                __nv_bfloat16 t1 = __float2bfloat16(v1);
                pfh[j16][a] = pack_bf16(v0, v1);
                pfl[j16][a] = pack_bf16(v0 - __bfloat162float(t0),
                                        v1 - __bfloat162float(t1));
            }
        }

        // ---- O += P V (3-term split); V via trans ldmatrix ----
        const int j16max = diag ? wid : 3;
        for (int j16 = 0; j16 <= j16max; j16++) {
            #pragma unroll
            for (int nb = 0; nb < 4; nb++) {
                uint32_t addr = kvb + OFF_VH
                              + (j16 * 16 + vb_row) * FROW
                              + (nb * 16 + vb_col) * 2;
                uint32_t vhf[4], vlf[4];
                LDSM4T(vhf, addr);
                LDSM4T(vlf, addr + FARR);
                MMA_BF16(oacc[2*nb],   pfh[j16], vhf);
                MMA_BF16(oacc[2*nb],   pfh[j16], vlf);
                MMA_BF16(oacc[2*nb],   pfl[j16], vhf);
                MMA_BF16(oacc[2*nb+1], pfh[j16], vhf + 2);
                MMA_BF16(oacc[2*nb+1], pfh[j16], vlf + 2);
                MMA_BF16(oacc[2*nb+1], pfl[j16], vhf + 2);
            }
        }

        __syncthreads();
        cur ^= 1;
    }

    // ---- epilogue: normalize, split to bf16 hi/lo, store directly ----
    float inv0 = 1.f / l0, inv1 = 1.f / l1;
    size_t row0 = (size_t)(b * TT + qt * 64 + wid * 16 + (lane >> 2));
    #pragma unroll
    for (int nb = 0; nb < 8; nb++) {
        size_t col = (size_t)(h * 64 + nb * 8 + 2 * (lane & 3));
        {
            float v0 = oacc[nb][0] * inv0, v1 = oacc[nb][1] * inv0;
            __nv_bfloat16 t0 = __float2bfloat16(v0);
            __nv_bfloat16 t1 = __float2bfloat16(v1);
            *reinterpret_cast<uint32_t*>(&yh[row0 * EE + col]) = pack_bf16(v0, v1);
            *reinterpret_cast<uint32_t*>(&yl[row0 * EE + col]) =
                pack_bf16(v0 - __bfloat162float(t0), v1 - __bfloat162float(t1));
        }
        {
            float v0 = oacc[nb][2] * inv1, v1 = oacc[nb][3] * inv1;
            __nv_bfloat16 t0 = __float2bfloat16(v0);
            __nv_bfloat16 t1 = __float2bfloat16(v1);
            *reinterpret_cast<uint32_t*>(&yh[(row0 + 8) * EE + col]) = pack_bf16(v0, v1);
            *reinterpret_cast<uint32_t*>(&yl[(row0 + 8) * EE + col]) =
                pack_bf16(v0 - __bfloat162float(t0), v1 - __bfloat162float(t1));
        }
    }
}

// ---------------------------------------------------------------------------
// kernel_launch — 5 launches; flash_mma is #4 (profiler window)
// ---------------------------------------------------------------------------
extern "C" void kernel_launch(void* const* d_in, const int* in_sizes, int n_in,
                              void* d_out, int out_size)
{
    const float* x   = (const float*)d_in[0];
    const float* cs  = (const float*)d_in[1];
    const float* sn  = (const float*)d_in[2];
    const float* Wq  = (const float*)d_in[3];
    const float* Wk  = (const float*)d_in[4];
    const float* Wv  = (const float*)d_in[5];
    const float* Wo  = (const float*)d_in[6];
    float* out = (float*)d_out;

    float *q, *k, *v;
    cudaGetSymbolAddress((void**)&q, g_q);
    cudaGetSymbolAddress((void**)&k, g_k);
    cudaGetSymbolAddress((void**)&v, g_v);

    __nv_bfloat16 *xh, *xl, *yh, *yl;
    __nv_bfloat16 *wqh, *wql, *wkh, *wkl, *wvh, *wvl, *woh, *wol;
    __nv_bfloat16 *qhp, *qlp, *khp, *klp, *vhp, *vlp;
    cudaGetSymbolAddress((void**)&xh,  g_x_hi);  cudaGetSymbolAddress((void**)&xl,  g_x_lo);
    cudaGetSymbolAddress((void**)&yh,  g_y_hi);  cudaGetSymbolAddress((void**)&yl,  g_y_lo);
    cudaGetSymbolAddress((void**)&wqh, g_wq_hi); cudaGetSymbolAddress((void**)&wql, g_wq_lo);
    cudaGetSymbolAddress((void**)&wkh, g_wk_hi); cudaGetSymbolAddress((void**)&wkl, g_wk_lo);
    cudaGetSymbolAddress((void**)&wvh, g_wv_hi); cudaGetSymbolAddress((void**)&wvl, g_wv_lo);
    cudaGetSymbolAddress((void**)&woh, g_wo_hi); cudaGetSymbolAddress((void**)&wol, g_wo_lo);
    cudaGetSymbolAddress((void**)&qhp, g_qh);    cudaGetSymbolAddress((void**)&qlp, g_ql);
    cudaGetSymbolAddress((void**)&khp, g_kh);    cudaGetSymbolAddress((void**)&klp, g_kl);
    cudaGetSymbolAddress((void**)&vhp, g_vh);    cudaGetSymbolAddress((void**)&vlp, g_vl);

    cudaFuncSetAttribute(gemm_mma, cudaFuncAttributeMaxDynamicSharedMemorySize,
                         GEMM_SMEM);
    cudaFuncSetAttribute(gemm_mma_qkv, cudaFuncAttributeMaxDynamicSharedMemorySize,
                         GEMM_SMEM);
    cudaFuncSetAttribute(flash_mma, cudaFuncAttributeMaxDynamicSharedMemorySize,
                         FLASH_SMEM);

    // #1: all input splits
    {
        SplitArgs a;
        a.in[0] = x;  a.hi[0] = xh;  a.lo[0] = xl;  a.n4[0] = MM * EE / 4;
        a.in[1] = Wq; a.hi[1] = wqh; a.lo[1] = wql; a.n4[1] = EE * EE / 4;
        a.in[2] = Wk; a.hi[2] = wkh; a.lo[2] = wkl; a.n4[2] = KVH * HD * EE / 4;
        a.in[3] = Wv; a.hi[3] = wvh; a.lo[3] = wvl; a.n4[3] = KVH * HD * EE / 4;
        a.in[4] = Wo; a.hi[4] = woh; a.lo[4] = wol; a.n4[4] = EE * EE / 4;
        int maxb = (MM * EE / 4 + 255) / 256;
        split_all<<<dim3(maxb, 5), 256>>>(a);
    }

    // #2: Q + K + V projections
    gemm_mma_qkv<<<dim3(12, MM / 128), 256, GEMM_SMEM>>>(
        xh, xl, wqh, wql, wkh, wkl, wvh, wvl, q, k, v);

    // #3: rope q/k + v split
    {
        int maxb = (BB * TT * HH * 32 + 255) / 256;
        rope_all<<<dim3(maxb, 3), 256>>>(q, k, v, cs, sn,
                                         qhp, qlp, khp, klp, vhp, vlp);
    }

    // #4: flash attention (writes yh/yl directly) — profiler window
    flash_mma<<<dim3(TT / 64, HH, BB), 128, FLASH_SMEM>>>(
        qhp, qlp, khp, klp, vhp, vlp, yh, yl);

    // #5: output projection
    gemm_mma<<<dim3(EE / 128, MM / 128), 256, GEMM_SMEM>>>(yh, yl, woh, wol, out, MM, EE, EE);
}

// round 8
// speedup vs baseline: 1.0474x; 1.0474x over previous
#include <cuda_runtime.h>
#include <cuda_bf16.h>
#include <math.h>
#include <stdint.h>

// Problem constants
#define BB 2
#define TT 2048
#define EE 1024
#define HH 16
#define KVH 4
#define HD 64
#define GG 4           // H / KVH
#define MM (BB*TT)     // 4096 rows

// ---------------------------------------------------------------------------
// Device scratch (allocation-free rule: __device__ globals)
// ---------------------------------------------------------------------------
__device__ float g_q[MM*EE];
__device__ float g_k[MM*KVH*HD];
__device__ float g_v[MM*KVH*HD];

__device__ __nv_bfloat16 g_x_hi[MM*EE],      g_x_lo[MM*EE];
__device__ __nv_bfloat16 g_y_hi[MM*EE],      g_y_lo[MM*EE];
__device__ __nv_bfloat16 g_wq_hi[EE*EE],     g_wq_lo[EE*EE];
__device__ __nv_bfloat16 g_wk_hi[KVH*HD*EE], g_wk_lo[KVH*HD*EE];
__device__ __nv_bfloat16 g_wv_hi[KVH*HD*EE], g_wv_lo[KVH*HD*EE];
__device__ __nv_bfloat16 g_wo_hi[EE*EE],     g_wo_lo[EE*EE];

__device__ __nv_bfloat16 g_qh[MM*EE],        g_ql[MM*EE];
__device__ __nv_bfloat16 g_kh[MM*KVH*HD],    g_kl[MM*KVH*HD];
__device__ __nv_bfloat16 g_vh[MM*KVH*HD],    g_vl[MM*KVH*HD];

// ---------------------------------------------------------------------------
// PTX helpers
// ---------------------------------------------------------------------------
__device__ __forceinline__ uint32_t smem_u32(const void* p) {
    uint32_t a;
    asm("{ .reg .u64 t; cvta.to.shared.u64 t, %1; cvt.u32.u64 %0, t; }"
        : "=r"(a) : "l"(p));
    return a;
}

#define LDSM4(r, addr) \
    asm volatile("ldmatrix.sync.aligned.m8n8.x4.shared.b16 {%0,%1,%2,%3}, [%4];" \
        : "=r"((r)[0]), "=r"((r)[1]), "=r"((r)[2]), "=r"((r)[3]) : "r"(addr))

#define LDSM4T(r, addr) \
    asm volatile("ldmatrix.sync.aligned.m8n8.x4.trans.shared.b16 {%0,%1,%2,%3}, [%4];" \
        : "=r"((r)[0]), "=r"((r)[1]), "=r"((r)[2]), "=r"((r)[3]) : "r"(addr))

#define MMA_BF16(d, a, b) \
    asm volatile("mma.sync.aligned.m16n8k16.row.col.f32.bf16.bf16.f32 " \
        "{%0,%1,%2,%3}, {%4,%5,%6,%7}, {%8,%9}, {%0,%1,%2,%3};" \
        : "+f"((d)[0]), "+f"((d)[1]), "+f"((d)[2]), "+f"((d)[3]) \
        : "r"((a)[0]), "r"((a)[1]), "r"((a)[2]), "r"((a)[3]), \
          "r"((b)[0]), "r"((b)[1]))

#define CP_ASYNC16(dst, src) \
    asm volatile("cp.async.cg.shared.global [%0], [%1], 16;" \
        :: "r"(dst), "l"(src))
#define CP_COMMIT() asm volatile("cp.async.commit_group;" ::: "memory")
#define CP_WAIT0()  asm volatile("cp.async.wait_group 0;" ::: "memory")
#define CP_WAIT1()  asm volatile("cp.async.wait_group 1;" ::: "memory")

__device__ __forceinline__ uint32_t pack_bf16(float lo, float hi) {
    __nv_bfloat162 t = __float22bfloat162_rn(make_float2(lo, hi));
    return *reinterpret_cast<uint32_t*>(&t);
}

// ---------------------------------------------------------------------------
// Batched split
// ---------------------------------------------------------------------------
struct SplitArgs {
    const float*   in[5];
    __nv_bfloat16* hi[5];
    __nv_bfloat16* lo[5];
    int            n4[5];
};

__device__ __forceinline__ void split_one(const float* __restrict__ in,
                                          __nv_bfloat16* __restrict__ hi,
                                          __nv_bfloat16* __restrict__ lo, int i)
{
    float4 v = reinterpret_cast<const float4*>(in)[i];
    float f[4] = {v.x, v.y, v.z, v.w};
    __nv_bfloat16 h0 = __float2bfloat16(f[0]);
    __nv_bfloat16 h1 = __float2bfloat16(f[1]);
    __nv_bfloat16 h2 = __float2bfloat16(f[2]);
    __nv_bfloat16 h3 = __float2bfloat16(f[3]);
    __nv_bfloat16 l0 = __float2bfloat16(f[0] - __bfloat162float(h0));
    __nv_bfloat16 l1 = __float2bfloat16(f[1] - __bfloat162float(h1));
    __nv_bfloat16 l2 = __float2bfloat16(f[2] - __bfloat162float(h2));
    __nv_bfloat16 l3 = __float2bfloat16(f[3] - __bfloat162float(h3));
    uint32_t ph0 = (uint32_t)__bfloat16_as_ushort(h0) | ((uint32_t)__bfloat16_as_ushort(h1) << 16);
    uint32_t ph1 = (uint32_t)__bfloat16_as_ushort(h2) | ((uint32_t)__bfloat16_as_ushort(h3) << 16);
    uint32_t pl0 = (uint32_t)__bfloat16_as_ushort(l0) | ((uint32_t)__bfloat16_as_ushort(l1) << 16);
    uint32_t pl1 = (uint32_t)__bfloat16_as_ushort(l2) | ((uint32_t)__bfloat16_as_ushort(l3) << 16);
    reinterpret_cast<uint2*>(hi)[i] = make_uint2(ph0, ph1);
    reinterpret_cast<uint2*>(lo)[i] = make_uint2(pl0, pl1);
}

__global__ void split_all(SplitArgs a)
{
    int seg = blockIdx.y;
    int i   = blockIdx.x * blockDim.x + threadIdx.x;
    if (i >= a.n4[seg]) return;
    split_one(a.in[seg], a.hi[seg], a.lo[seg], i);
}

// ---------------------------------------------------------------------------
// rope_all: y=0 q rope+split, y=1 k rope+split, y=2 v plain split
// ---------------------------------------------------------------------------
__global__ void rope_all(const float* __restrict__ q,
                         const float* __restrict__ k,
                         const float* __restrict__ v,
                         const float* __restrict__ c,
                         const float* __restrict__ s,
                         __nv_bfloat16* __restrict__ qh, __nv_bfloat16* __restrict__ ql,
                         __nv_bfloat16* __restrict__ kh, __nv_bfloat16* __restrict__ kl,
                         __nv_bfloat16* __restrict__ vh, __nv_bfloat16* __restrict__ vl)
{
    int seg = blockIdx.y;
    int idx = blockIdx.x * blockDim.x + threadIdx.x;
    if (seg == 2) {
        int n4 = MM * KVH * HD / 4;
        if (idx >= n4) return;
        split_one(v, vh, vl, idx);
        return;
    }
    const float* x = (seg == 0) ? q : k;
    __nv_bfloat16* hi = (seg == 0) ? qh : kh;
    __nv_bfloat16* lo = (seg == 0) ? ql : kl;
    int heads = (seg == 0) ? HH : KVH;
    int n = BB * TT * heads * 32;
    if (idx >= n) return;

    int d  = idx & 31;
    int r  = idx >> 5;
    int h  = r % heads;
    int bt = r / heads;

    const float* p  = x + ((size_t)bt * heads + h) * 64;
    const float* cp = c + (size_t)bt * 64;
    const float* sp = s + (size_t)bt * 64;

    float x1 = p[d];
    float x2 = p[d + 32];
    float y1 = x1 * cp[d]      - x2 * sp[d];
    float y2 = x2 * cp[d + 32] + x1 * sp[d + 32];

    size_t o = ((size_t)bt * heads + h) * 64;
    __nv_bfloat16 h1 = __float2bfloat16(y1);
    __nv_bfloat16 h2 = __float2bfloat16(y2);
    hi[o + d]      = h1;
    hi[o + d + 32] = h2;
    lo[o + d]      = __float2bfloat16(y1 - __bfloat162float(h1));
    lo[o + d + 32] = __float2bfloat16(y2 - __bfloat162float(h2));
}

// ---------------------------------------------------------------------------
// mma.sync GEMM body: C[M,N] = A[M,K] * W[N,K]^T, bf16x2 split (hh+hl+lh)
// ---------------------------------------------------------------------------
#define TILE_BYTES   10240
#define BUF_BYTES    (4*TILE_BYTES)
#define GEMM_SMEM    (2*BUF_BYTES)

__device__ __forceinline__ void issue_tile(
    uint32_t sbuf,
    const __nv_bfloat16* __restrict__ Ahi, const __nv_bfloat16* __restrict__ Alo,
    const __nv_bfloat16* __restrict__ Bhi, const __nv_bfloat16* __restrict__ Blo,
    int m0, int n0, int k0, int K, int tid)
{
    #pragma unroll
    for (int it = 0; it < 2; it++) {
        int idx = tid + it * 256;
        int r   = idx >> 2;
        int c8  = idx & 3;
        uint32_t so = (uint32_t)(r * 80 + c8 * 16);
        size_t ga = (size_t)(m0 + r) * K + k0 + c8 * 8;
        size_t gb = (size_t)(n0 + r) * K + k0 + c8 * 8;
        CP_ASYNC16(sbuf + so,                 (const char*)(Ahi + ga));
        CP_ASYNC16(sbuf + TILE_BYTES + so,    (const char*)(Alo + ga));
        CP_ASYNC16(sbuf + 2*TILE_BYTES + so,  (const char*)(Bhi + gb));
        CP_ASYNC16(sbuf + 3*TILE_BYTES + so,  (const char*)(Blo + gb));
    }
}

__device__ __forceinline__ void gemm_body(
    uint32_t sbase,
    const __nv_bfloat16* __restrict__ Ahi, const __nv_bfloat16* __restrict__ Alo,
    const __nv_bfloat16* __restrict__ Bhi, const __nv_bfloat16* __restrict__ Blo,
    float* __restrict__ C, int M, int N, int K, int m0, int n0)
{
    const int tid  = threadIdx.x;
    const int lane = tid & 31;
    const int wid  = tid >> 5;
    const int wm   = wid >> 2;
    const int wn   = wid & 3;

    float acc[4][4][4];
    #pragma unroll
    for (int i = 0; i < 4; i++)
        #pragma unroll
        for (int j = 0; j < 4; j++)
            #pragma unroll
            for (int r = 0; r < 4; r++) acc[i][j][r] = 0.f;

    const uint32_t a_row  = (uint32_t)(wm * 64 + (lane & 15));
    const uint32_t a_k8   = (uint32_t)(lane >> 4);
    const uint32_t b_row  = (uint32_t)(wn * 32 + (lane & 7) + ((lane >> 4) << 3));
    const uint32_t b_k8   = (uint32_t)((lane >> 3) & 1);

    const int NK = K / 32;
    issue_tile(sbase, Ahi, Alo, Bhi, Blo, m0, n0, 0, K, tid);
    CP_COMMIT();

    for (int kt = 0; kt < NK; kt++) {
        CP_WAIT0();
        __syncthreads();
        if (kt + 1 < NK) {
            issue_tile(sbase + (uint32_t)((kt + 1) & 1) * BUF_BYTES,
                       Ahi, Alo, Bhi, Blo, m0, n0, (kt + 1) * 32, K, tid);
            CP_COMMIT();
        }
        const uint32_t buf = sbase + (uint32_t)(kt & 1) * BUF_BYTES;

        #pragma unroll
        for (int ks = 0; ks < 2; ks++) {
            uint32_t ah[4][4], al[4][4], bh[2][4], bl[2][4];
            #pragma unroll
            for (int mb = 0; mb < 4; mb++) {
                uint32_t addr = buf + (a_row + mb * 16) * 80
                                    + (ks * 2 + a_k8) * 16;
                LDSM4(ah[mb], addr);
                LDSM4(al[mb], addr + TILE_BYTES);
            }
            #pragma unroll
            for (int nb = 0; nb < 2; nb++) {
                uint32_t addr = buf + 2*TILE_BYTES
                                    + (b_row + nb * 16) * 80
                                    + (ks * 2 + b_k8) * 16;
                LDSM4(bh[nb], addr);
                LDSM4(bl[nb], addr + TILE_BYTES);
            }
            #pragma unroll
            for (int mb = 0; mb < 4; mb++) {
                #pragma unroll
                for (int n8 = 0; n8 < 4; n8++) {
                    uint32_t* Bh = &bh[n8 >> 1][(n8 & 1) * 2];
                    uint32_t* Bl = &bl[n8 >> 1][(n8 & 1) * 2];
                    MMA_BF16(acc[mb][n8], ah[mb], Bh);
                    MMA_BF16(acc[mb][n8], ah[mb], Bl);
                    MMA_BF16(acc[mb][n8], al[mb], Bh);
                }
            }
        }
    }

    #pragma unroll
    for (int mb = 0; mb < 4; mb++) {
        int row = m0 + wm * 64 + mb * 16 + (lane >> 2);
        #pragma unroll
        for (int n8 = 0; n8 < 4; n8++) {
            int col = n0 + wn * 32 + n8 * 8 + (lane & 3) * 2;
            *reinterpret_cast<float2*>(&C[(size_t)row * N + col]) =
                make_float2(acc[mb][n8][0], acc[mb][n8][1]);
            *reinterpret_cast<float2*>(&C[(size_t)(row + 8) * N + col]) =
                make_float2(acc[mb][n8][2], acc[mb][n8][3]);
        }
    }
}

__global__ __launch_bounds__(256) void gemm_mma(
    const __nv_bfloat16* __restrict__ Ahi, const __nv_bfloat16* __restrict__ Alo,
    const __nv_bfloat16* __restrict__ Bhi, const __nv_bfloat16* __restrict__ Blo,
    float* __restrict__ C, int M, int N, int K)
{
    extern __shared__ char sm[];
    gemm_body(smem_u32(sm), Ahi, Alo, Bhi, Blo, C, M, N, K,
              blockIdx.y * 128, blockIdx.x * 128);
}

// combined Q/K/V projections
__global__ __launch_bounds__(256) void gemm_mma_qkv(
    const __nv_bfloat16* __restrict__ Ahi, const __nv_bfloat16* __restrict__ Alo,
    const __nv_bfloat16* __restrict__ Wqh, const __nv_bfloat16* __restrict__ Wql,
    const __nv_bfloat16* __restrict__ Wkh, const __nv_bfloat16* __restrict__ Wkl,
    const __nv_bfloat16* __restrict__ Wvh, const __nv_bfloat16* __restrict__ Wvl,
    float* __restrict__ Cq, float* __restrict__ Ck, float* __restrict__ Cv)
{
    extern __shared__ char sm[];
    int bx = blockIdx.x;
    const __nv_bfloat16 *Bh, *Bl;
    float* C;
    int N, n0;
    if (bx < 8)       { Bh = Wqh; Bl = Wql; C = Cq; N = EE;       n0 = bx * 128; }
    else if (bx < 10) { Bh = Wkh; Bl = Wkl; C = Ck; N = KVH * HD; n0 = (bx - 8) * 128; }
    else              { Bh = Wvh; Bl = Wvl; C = Cv; N = KVH * HD; n0 = (bx - 10) * 128; }
    gemm_body(smem_u32(sm), Ahi, Alo, Bh, Bl, C, MM, N, EE,
              blockIdx.y * 128, n0);
}

// ---------------------------------------------------------------------------
// Flash attention, 1 head per CTA, bf16 hi/lo split, BM=BN=64.
// 128 threads = 4 warps; 3 CTAs/SM (Q smem overlaid on KV buffer 1, streamed
// P-pack keeps regs ~140). Fully unrolled S/PV loops with uniform diag skip.
// ---------------------------------------------------------------------------
#define FROW      144
#define FARR      (64*FROW)            // 9216
#define KVBUF     (4*FARR)             // per-buffer: kh, kl, vh, vl
#define OFF_KH    0
#define OFF_KL    FARR
#define OFF_VH    (2*FARR)
#define OFF_VL    (3*FARR)
// Q overlays KV buffer 1 (read into frags before buffer 1 is first written)
#define SM_QH     KVBUF
#define SM_QL     (KVBUF + FARR)
#define FLASH_SMEM (8*FARR)            // 73728; 3 CTAs/SM = 221184 < 228K

#define SCALE_L2E 0.180336879f         // 0.125 * log2(e)

__device__ __forceinline__ void flash_load_kv(
    uint32_t kb,
    const __nv_bfloat16* __restrict__ kh, const __nv_bfloat16* __restrict__ kl,
    const __nv_bfloat16* __restrict__ vh, const __nv_bfloat16* __restrict__ vl,
    int b, int kt, int kvh, int tid)
{
    #pragma unroll
    for (int it = 0; it < 4; it++) {
        int idx = tid + it * 128;
        int r   = idx >> 3;
        int c   = idx & 7;
        size_t g = (size_t)(b * TT + kt * 64 + r) * (KVH * HD) + kvh * 64 + c * 8;
        uint32_t so = (uint32_t)(r * FROW + c * 16);
        CP_ASYNC16(kb + OFF_KH + so, (const char*)(kh + g));
        CP_ASYNC16(kb + OFF_KL + so, (const char*)(kl + g));
        CP_ASYNC16(kb + OFF_VH + so, (const char*)(vh + g));
        CP_ASYNC16(kb + OFF_VL + so, (const char*)(vl + g));
    }
}

__global__ __launch_bounds__(128, 3) void flash_mma(
    const __nv_bfloat16* __restrict__ qh, const __nv_bfloat16* __restrict__ ql,
    const __nv_bfloat16* __restrict__ kh, const __nv_bfloat16* __restrict__ kl,
    const __nv_bfloat16* __restrict__ vh, const __nv_bfloat16* __restrict__ vl,
    __nv_bfloat16* __restrict__ yh, __nv_bfloat16* __restrict__ yl)
{
    extern __shared__ char sm[];
    const uint32_t sb = smem_u32(sm);
    const int tid  = threadIdx.x;
    const int lane = tid & 31;
    const int wid  = tid >> 5;
    const int qt   = (int)(gridDim.x - 1 - blockIdx.x);   // big tiles first
    const int h    = blockIdx.y;
    const int b    = blockIdx.z;
    const int kvh  = h / GG;

    // prologue: Q (hi+lo) into buffer-1 region, KV tile 0 into buffer 0
    #pragma unroll
    for (int it = 0; it < 4; it++) {
        int idx = tid + it * 128;
        int r   = idx >> 3;
        int c   = idx & 7;
        size_t g = (size_t)(b * TT + qt * 64 + r) * EE + h * 64 + c * 8;
        uint32_t so = (uint32_t)(r * FROW + c * 16);
        CP_ASYNC16(sb + SM_QH + so, (const char*)(qh + g));
        CP_ASYNC16(sb + SM_QL + so, (const char*)(ql + g));
    }
    CP_COMMIT();
    flash_load_kv(sb, kh, kl, vh, vl, b, 0, kvh, tid);
    CP_COMMIT();

    CP_WAIT1();          // Q group complete
    __syncthreads();

    // Q A-fragments resident; after this sync, buffer 1 may be overwritten
    uint32_t qfh[4][4], qfl[4][4];
    {
        const uint32_t a_row = (uint32_t)(wid * 16 + (lane & 15));
        const uint32_t a_k8  = (uint32_t)(lane >> 4);
        #pragma unroll
        for (int ks = 0; ks < 4; ks++) {
            uint32_t addr = sb + SM_QH + a_row * FROW + (ks * 2 + a_k8) * 16;
            LDSM4(qfh[ks], addr);
            LDSM4(qfl[ks], addr + FARR);
        }
    }
    __syncthreads();

    const uint32_t kb_row = (uint32_t)((lane & 7) + ((lane >> 4) << 3));
    const uint32_t kb_k8  = (uint32_t)((lane >> 3) & 1);
    const uint32_t vb_row = (uint32_t)((lane & 7) + (((lane >> 3) & 1) << 3));
    const uint32_t vb_col = (uint32_t)((lane >> 4) << 3);

    float oacc[8][4];
    #pragma unroll
    for (int nb = 0; nb < 8; nb++)
        #pragma unroll
        for (int j = 0; j < 4; j++) oacc[nb][j] = 0.f;
    float m0 = -INFINITY, m1 = -INFINITY, l0 = 0.f, l1 = 0.f;

    int cur = 0;
    for (int kt = 0; kt <= qt; kt++) {
        if (kt + 1 <= qt) {
            flash_load_kv(sb + (uint32_t)(cur ^ 1) * KVBUF,
                          kh, kl, vh, vl, b, kt + 1, kvh, tid);
            CP_COMMIT();
            CP_WAIT1();
        } else {
            CP_WAIT0();
        }
        __syncthreads();
        const uint32_t kvb = sb + (uint32_t)cur * KVBUF;
        const bool diag = (kt == qt);

        // ---- S = Q K^T (3-term split), fully unrolled, uniform diag skip ----
        float sacc[8][4];
        #pragma unroll
        for (int nb = 0; nb < 8; nb++)
            #pragma unroll
            for (int j = 0; j < 4; j++) sacc[nb][j] = 0.f;

        #pragma unroll
        for (int ks = 0; ks < 4; ks++) {
            #pragma unroll
            for (int nb = 0; nb < 4; nb++) {
                if (diag && nb > wid) continue;     // uniform per warp
                uint32_t addr = kvb + OFF_KH + (kb_row + nb * 16) * FROW
                                            + (ks * 2 + kb_k8) * 16;
                uint32_t bh[4], bl[4];
                LDSM4(bh, addr);
                LDSM4(bl, addr + FARR);
                MMA_BF16(sacc[2*nb],   qfh[ks], bh);
                MMA_BF16(sacc[2*nb],   qfh[ks], bl);
                MMA_BF16(sacc[2*nb],   qfl[ks], bh);
                MMA_BF16(sacc[2*nb+1], qfh[ks], bh + 2);
                MMA_BF16(sacc[2*nb+1], qfh[ks], bl + 2);
                MMA_BF16(sacc[2*nb+1], qfl[ks], bh + 2);
            }
        }

        // ---- scale (base-2) + causal mask (covers skipped blocks too) ----
        #pragma unroll
        for (int nb = 0; nb < 8; nb++)
            #pragma unroll
            for (int j = 0; j < 4; j++) sacc[nb][j] *= SCALE_L2E;
        if (diag) {
            #pragma unroll
            for (int nb = 0; nb < 8; nb++)
                #pragma unroll
                for (int j = 0; j < 4; j++) {
                    int n_loc = nb * 8 + 2 * (lane & 3) + (j & 1);
                    int m_loc = wid * 16 + (lane >> 2) + ((j >> 1) << 3);
                    if (n_loc > m_loc) sacc[nb][j] = -1e30f;
                }
        }

        // ---- online softmax (base-2) ----
        float mx0 = -INFINITY, mx1 = -INFINITY;
        #pragma unroll
        for (int nb = 0; nb < 8; nb++) {
            mx0 = fmaxf(mx0, fmaxf(sacc[nb][0], sacc[nb][1]));
            mx1 = fmaxf(mx1, fmaxf(sacc[nb][2], sacc[nb][3]));
        }
        mx0 = fmaxf(mx0, __shfl_xor_sync(0xffffffffu, mx0, 1));
        mx0 = fmaxf(mx0, __shfl_xor_sync(0xffffffffu, mx0, 2));
        mx1 = fmaxf(mx1, __shfl_xor_sync(0xffffffffu, mx1, 1));
        mx1 = fmaxf(mx1, __shfl_xor_sync(0xffffffffu, mx1, 2));

        float mn0 = fmaxf(m0, mx0), mn1 = fmaxf(m1, mx1);
        float al0 = exp2f(m0 - mn0), al1 = exp2f(m1 - mn1);
        m0 = mn0; m1 = mn1;

        float sum0 = 0.f, sum1 = 0.f;
        #pragma unroll
        for (int nb = 0; nb < 8; nb++) {
            sacc[nb][0] = exp2f(sacc[nb][0] - mn0);
            sacc[nb][1] = exp2f(sacc[nb][1] - mn0);
            sacc[nb][2] = exp2f(sacc[nb][2] - mn1);
            sacc[nb][3] = exp2f(sacc[nb][3] - mn1);
            sum0 += sacc[nb][0] + sacc[nb][1];
            sum1 += sacc[nb][2] + sacc[nb][3];
        }
        sum0 += __shfl_xor_sync(0xffffffffu, sum0, 1);
        sum0 += __shfl_xor_sync(0xffffffffu, sum0, 2);
        sum1 += __shfl_xor_sync(0xffffffffu, sum1, 1);
        sum1 += __shfl_xor_sync(0xffffffffu, sum1, 2);
        l0 = l0 * al0 + sum0;
        l1 = l1 * al1 + sum1;

        #pragma unroll
        for (int nb = 0; nb < 8; nb++) {
            oacc[nb][0] *= al0; oacc[nb][1] *= al0;
            oacc[nb][2] *= al1; oacc[nb][3] *= al1;
        }

        // ---- streamed pack + PV: per j16, pack 8 regs then consume ----
        #pragma unroll
        for (int j16 = 0; j16 < 4; j16++) {
            if (diag && j16 > wid) continue;        // P block is all zeros
            uint32_t pfh[4], pfl[4];
            {
                float* c0 = sacc[2*j16];
                float* c1 = sacc[2*j16 + 1];
                #pragma unroll
                for (int a = 0; a < 4; a++) {
                    float v0 = (a < 2) ? c0[(a & 1) * 2]     : c1[(a & 1) * 2];
                    float v1 = (a < 2) ? c0[(a & 1) * 2 + 1] : c1[(a & 1) * 2 + 1];
                    __nv_bfloat16 t0 = __float2bfloat16(v0);
                    __nv_bfloat16 t1 = __float2bfloat16(v1);
                    pfh[a] = pack_bf16(v0, v1);
                    pfl[a] = pack_bf16(v0 - __bfloat162float(t0),
                                       v1 - __bfloat162float(t1));
                }
            }
            #pragma unroll
            for (int nb = 0; nb < 4; nb++) {
                uint32_t addr = kvb + OFF_VH
                              + (j16 * 16 + vb_row) * FROW
                              + (nb * 16 + vb_col) * 2;
                uint32_t vhf[4], vlf[4];
                LDSM4T(vhf, addr);
                LDSM4T(vlf, addr + FARR);
                MMA_BF16(oacc[2*nb],   pfh, vhf);
                MMA_BF16(oacc[2*nb],   pfh, vlf);
                MMA_BF16(oacc[2*nb],   pfl, vhf);
                MMA_BF16(oacc[2*nb+1], pfh, vhf + 2);
                MMA_BF16(oacc[2*nb+1], pfh, vlf + 2);
                MMA_BF16(oacc[2*nb+1], pfl, vhf + 2);
            }
        }

        __syncthreads();
        cur ^= 1;
    }

    // ---- epilogue: normalize, split to bf16 hi/lo, store directly ----
    float inv0 = 1.f / l0, inv1 = 1.f / l1;
    size_t row0 = (size_t)(b * TT + qt * 64 + wid * 16 + (lane >> 2));
    #pragma unroll
    for (int nb = 0; nb < 8; nb++) {
        size_t col = (size_t)(h * 64 + nb * 8 + 2 * (lane & 3));
        {
            float v0 = oacc[nb][0] * inv0, v1 = oacc[nb][1] * inv0;
            __nv_bfloat16 t0 = __float2bfloat16(v0);
            __nv_bfloat16 t1 = __float2bfloat16(v1);
            *reinterpret_cast<uint32_t*>(&yh[row0 * EE + col]) = pack_bf16(v0, v1);
            *reinterpret_cast<uint32_t*>(&yl[row0 * EE + col]) =
                pack_bf16(v0 - __bfloat162float(t0), v1 - __bfloat162float(t1));
        }
        {
            float v0 = oacc[nb][2] * inv1, v1 = oacc[nb][3] * inv1;
            __nv_bfloat16 t0 = __float2bfloat16(v0);
            __nv_bfloat16 t1 = __float2bfloat16(v1);
            *reinterpret_cast<uint32_t*>(&yh[(row0 + 8) * EE + col]) = pack_bf16(v0, v1);
            *reinterpret_cast<uint32_t*>(&yl[(row0 + 8) * EE + col]) =
                pack_bf16(v0 - __bfloat162float(t0), v1 - __bfloat162float(t1));
        }
    }
}

// ---------------------------------------------------------------------------
// kernel_launch — 5 launches; flash_mma is #4 (profiler window)
// ---------------------------------------------------------------------------
extern "C" void kernel_launch(void* const* d_in, const int* in_sizes, int n_in,
                              void* d_out, int out_size)
{
    const float* x   = (const float*)d_in[0];
    const float* cs  = (const float*)d_in[1];
    const float* sn  = (const float*)d_in[2];
    const float* Wq  = (const float*)d_in[3];
    const float* Wk  = (const float*)d_in[4];
    const float* Wv  = (const float*)d_in[5];
    const float* Wo  = (const float*)d_in[6];
    float* out = (float*)d_out;

    float *q, *k, *v;
    cudaGetSymbolAddress((void**)&q, g_q);
    cudaGetSymbolAddress((void**)&k, g_k);
    cudaGetSymbolAddress((void**)&v, g_v);

    __nv_bfloat16 *xh, *xl, *yh, *yl;
    __nv_bfloat16 *wqh, *wql, *wkh, *wkl, *wvh, *wvl, *woh, *wol;
    __nv_bfloat16 *qhp, *qlp, *khp, *klp, *vhp, *vlp;
    cudaGetSymbolAddress((void**)&xh,  g_x_hi);  cudaGetSymbolAddress((void**)&xl,  g_x_lo);
    cudaGetSymbolAddress((void**)&yh,  g_y_hi);  cudaGetSymbolAddress((void**)&yl,  g_y_lo);
    cudaGetSymbolAddress((void**)&wqh, g_wq_hi); cudaGetSymbolAddress((void**)&wql, g_wq_lo);
    cudaGetSymbolAddress((void**)&wkh, g_wk_hi); cudaGetSymbolAddress((void**)&wkl, g_wk_lo);
    cudaGetSymbolAddress((void**)&wvh, g_wv_hi); cudaGetSymbolAddress((void**)&wvl, g_wv_lo);
    cudaGetSymbolAddress((void**)&woh, g_wo_hi); cudaGetSymbolAddress((void**)&wol, g_wo_lo);
    cudaGetSymbolAddress((void**)&qhp, g_qh);    cudaGetSymbolAddress((void**)&qlp, g_ql);
    cudaGetSymbolAddress((void**)&khp, g_kh);    cudaGetSymbolAddress((void**)&klp, g_kl);
    cudaGetSymbolAddress((void**)&vhp, g_vh);    cudaGetSymbolAddress((void**)&vlp, g_vl);

    cudaFuncSetAttribute(gemm_mma, cudaFuncAttributeMaxDynamicSharedMemorySize,
                         GEMM_SMEM);
    cudaFuncSetAttribute(gemm_mma_qkv, cudaFuncAttributeMaxDynamicSharedMemorySize,
                         GEMM_SMEM);
    cudaFuncSetAttribute(flash_mma, cudaFuncAttributeMaxDynamicSharedMemorySize,
                         FLASH_SMEM);

    // #1: all input splits
    {
        SplitArgs a;
        a.in[0] = x;  a.hi[0] = xh;  a.lo[0] = xl;  a.n4[0] = MM * EE / 4;
        a.in[1] = Wq; a.hi[1] = wqh; a.lo[1] = wql; a.n4[1] = EE * EE / 4;
        a.in[2] = Wk; a.hi[2] = wkh; a.lo[2] = wkl; a.n4[2] = KVH * HD * EE / 4;
        a.in[3] = Wv; a.hi[3] = wvh; a.lo[3] = wvl; a.n4[3] = KVH * HD * EE / 4;
        a.in[4] = Wo; a.hi[4] = woh; a.lo[4] = wol; a.n4[4] = EE * EE / 4;
        int maxb = (MM * EE / 4 + 255) / 256;
        split_all<<<dim3(maxb, 5), 256>>>(a);
    }

    // #2: Q + K + V projections
    gemm_mma_qkv<<<dim3(12, MM / 128), 256, GEMM_SMEM>>>(
        xh, xl, wqh, wql, wkh, wkl, wvh, wvl, q, k, v);

    // #3: rope q/k + v split
    {
        int maxb = (BB * TT * HH * 32 + 255) / 256;
        rope_all<<<dim3(maxb, 3), 256>>>(q, k, v, cs, sn,
                                         qhp, qlp, khp, klp, vhp, vlp);
    }

    // #4: flash attention (writes yh/yl directly) — profiler window
    flash_mma<<<dim3(TT / 64, HH, BB), 128, FLASH_SMEM>>>(
        qhp, qlp, khp, klp, vhp, vlp, yh, yl);

    // #5: output projection
    gemm_mma<<<dim3(EE / 128, MM / 128), 256, GEMM_SMEM>>>(yh, yl, woh, wol, out, MM, EE, EE);
}

// round 9
// speedup vs baseline: 1.0777x; 1.0290x over previous
#include <cuda_runtime.h>
#include <cuda_bf16.h>
#include <math.h>
#include <stdint.h>

// Problem constants
#define BB 2
#define TT 2048
#define EE 1024
#define HH 16
#define KVH 4
#define HD 64
#define GG 4           // H / KVH
#define MM (BB*TT)     // 4096 rows

// ---------------------------------------------------------------------------
// Device scratch (allocation-free rule: __device__ globals)
// ---------------------------------------------------------------------------
__device__ float g_q[MM*EE];            // fp32 q (rope fused into flash)
__device__ float g_k[MM*KVH*HD];        // fp32 k (rope_k reads)

__device__ __nv_bfloat16 g_x_hi[MM*EE],      g_x_lo[MM*EE];
__device__ __nv_bfloat16 g_y_hi[MM*EE],      g_y_lo[MM*EE];
__device__ __nv_bfloat16 g_wq_hi[EE*EE],     g_wq_lo[EE*EE];
__device__ __nv_bfloat16 g_wk_hi[KVH*HD*EE], g_wk_lo[KVH*HD*EE];
__device__ __nv_bfloat16 g_wv_hi[KVH*HD*EE], g_wv_lo[KVH*HD*EE];
__device__ __nv_bfloat16 g_wo_hi[EE*EE],     g_wo_lo[EE*EE];

__device__ __nv_bfloat16 g_kh[MM*KVH*HD],    g_kl[MM*KVH*HD];
__device__ __nv_bfloat16 g_vh[MM*KVH*HD],    g_vl[MM*KVH*HD];

// ---------------------------------------------------------------------------
// PTX helpers
// ---------------------------------------------------------------------------
__device__ __forceinline__ uint32_t smem_u32(const void* p) {
    uint32_t a;
    asm("{ .reg .u64 t; cvta.to.shared.u64 t, %1; cvt.u32.u64 %0, t; }"
        : "=r"(a) : "l"(p));
    return a;
}

#define LDSM4(r, addr) \
    asm volatile("ldmatrix.sync.aligned.m8n8.x4.shared.b16 {%0,%1,%2,%3}, [%4];" \
        : "=r"((r)[0]), "=r"((r)[1]), "=r"((r)[2]), "=r"((r)[3]) : "r"(addr))

#define LDSM4T(r, addr) \
    asm volatile("ldmatrix.sync.aligned.m8n8.x4.trans.shared.b16 {%0,%1,%2,%3}, [%4];" \
        : "=r"((r)[0]), "=r"((r)[1]), "=r"((r)[2]), "=r"((r)[3]) : "r"(addr))

#define MMA_BF16(d, a, b) \
    asm volatile("mma.sync.aligned.m16n8k16.row.col.f32.bf16.bf16.f32 " \
        "{%0,%1,%2,%3}, {%4,%5,%6,%7}, {%8,%9}, {%0,%1,%2,%3};" \
        : "+f"((d)[0]), "+f"((d)[1]), "+f"((d)[2]), "+f"((d)[3]) \
        : "r"((a)[0]), "r"((a)[1]), "r"((a)[2]), "r"((a)[3]), \
          "r"((b)[0]), "r"((b)[1]))

#define CP_ASYNC16(dst, src) \
    asm volatile("cp.async.cg.shared.global [%0], [%1], 16;" \
        :: "r"(dst), "l"(src))
#define CP_COMMIT() asm volatile("cp.async.commit_group;" ::: "memory")
#define CP_WAIT0()  asm volatile("cp.async.wait_group 0;" ::: "memory")
#define CP_WAIT1()  asm volatile("cp.async.wait_group 1;" ::: "memory")

__device__ __forceinline__ uint32_t pack_bf16(float lo, float hi) {
    __nv_bfloat162 t = __float22bfloat162_rn(make_float2(lo, hi));
    return *reinterpret_cast<uint32_t*>(&t);
}

// pack to bf16x2 and also produce the residual pair using the packed halves
__device__ __forceinline__ void pack_split(float v0, float v1,
                                           uint32_t& ph, uint32_t& pl) {
    ph = pack_bf16(v0, v1);
    __nv_bfloat162 hb = *reinterpret_cast<__nv_bfloat162*>(&ph);
    pl = pack_bf16(v0 - __bfloat162float(hb.x), v1 - __bfloat162float(hb.y));
}

// ---------------------------------------------------------------------------
// Batched split (x + 4 weights)
// ---------------------------------------------------------------------------
struct SplitArgs {
    const float*   in[5];
    __nv_bfloat16* hi[5];
    __nv_bfloat16* lo[5];
    int            n4[5];
};

__device__ __forceinline__ void split_one(const float* __restrict__ in,
                                          __nv_bfloat16* __restrict__ hi,
                                          __nv_bfloat16* __restrict__ lo, int i)
{
    float4 v = reinterpret_cast<const float4*>(in)[i];
    uint32_t ph0, pl0, ph1, pl1;
    pack_split(v.x, v.y, ph0, pl0);
    pack_split(v.z, v.w, ph1, pl1);
    reinterpret_cast<uint2*>(hi)[i] = make_uint2(ph0, ph1);
    reinterpret_cast<uint2*>(lo)[i] = make_uint2(pl0, pl1);
}

__global__ void split_all(SplitArgs a)
{
    int seg = blockIdx.y;
    int i   = blockIdx.x * blockDim.x + threadIdx.x;
    if (i >= a.n4[seg]) return;
    split_one(a.in[seg], a.hi[seg], a.lo[seg], i);
}

// ---------------------------------------------------------------------------
// rope_k: k rope + split only (q fused into flash, v fused into gemm)
// ---------------------------------------------------------------------------
__global__ void rope_k(const float* __restrict__ k,
                       const float* __restrict__ c,
                       const float* __restrict__ s,
                       __nv_bfloat16* __restrict__ kh,
                       __nv_bfloat16* __restrict__ kl)
{
    int idx = blockIdx.x * blockDim.x + threadIdx.x;
    int n = BB * TT * KVH * 32;
    if (idx >= n) return;

    int d  = idx & 31;
    int r  = idx >> 5;
    int h  = r % KVH;
    int bt = r / KVH;

    const float* p  = k + ((size_t)bt * KVH + h) * 64;
    const float* cp = c + (size_t)bt * 64;
    const float* sp = s + (size_t)bt * 64;

    float x1 = p[d];
    float x2 = p[d + 32];
    float y1 = x1 * cp[d]      - x2 * sp[d];
    float y2 = x2 * cp[d + 32] + x1 * sp[d + 32];

    size_t o = ((size_t)bt * KVH + h) * 64;
    __nv_bfloat16 h1 = __float2bfloat16(y1);
    __nv_bfloat16 h2 = __float2bfloat16(y2);
    kh[o + d]      = h1;
    kh[o + d + 32] = h2;
    kl[o + d]      = __float2bfloat16(y1 - __bfloat162float(h1));
    kl[o + d + 32] = __float2bfloat16(y2 - __bfloat162float(h2));
}

// ---------------------------------------------------------------------------
// mma.sync GEMM body: C = A * W^T, bf16x2 split (hh+hl+lh).
// Epilogue: fp32 C OR direct bf16 hi/lo split (Ch/Cl) when Ch != nullptr.
// ---------------------------------------------------------------------------
#define TILE_BYTES   10240
#define BUF_BYTES    (4*TILE_BYTES)
#define GEMM_SMEM    (2*BUF_BYTES)

__device__ __forceinline__ void issue_tile(
    uint32_t sbuf,
    const __nv_bfloat16* __restrict__ Ahi, const __nv_bfloat16* __restrict__ Alo,
    const __nv_bfloat16* __restrict__ Bhi, const __nv_bfloat16* __restrict__ Blo,
    int m0, int n0, int k0, int K, int tid)
{
    #pragma unroll
    for (int it = 0; it < 2; it++) {
        int idx = tid + it * 256;
        int r   = idx >> 2;
        int c8  = idx & 3;
        uint32_t so = (uint32_t)(r * 80 + c8 * 16);
        size_t ga = (size_t)(m0 + r) * K + k0 + c8 * 8;
        size_t gb = (size_t)(n0 + r) * K + k0 + c8 * 8;
        CP_ASYNC16(sbuf + so,                 (const char*)(Ahi + ga));
        CP_ASYNC16(sbuf + TILE_BYTES + so,    (const char*)(Alo + ga));
        CP_ASYNC16(sbuf + 2*TILE_BYTES + so,  (const char*)(Bhi + gb));
        CP_ASYNC16(sbuf + 3*TILE_BYTES + so,  (const char*)(Blo + gb));
    }
}

__device__ __forceinline__ void gemm_body(
    uint32_t sbase,
    const __nv_bfloat16* __restrict__ Ahi, const __nv_bfloat16* __restrict__ Alo,
    const __nv_bfloat16* __restrict__ Bhi, const __nv_bfloat16* __restrict__ Blo,
    float* __restrict__ C,
    __nv_bfloat16* __restrict__ Ch, __nv_bfloat16* __restrict__ Cl,
    int M, int N, int K, int m0, int n0)
{
    const int tid  = threadIdx.x;
    const int lane = tid & 31;
    const int wid  = tid >> 5;
    const int wm   = wid >> 2;
    const int wn   = wid & 3;

    float acc[4][4][4];
    #pragma unroll
    for (int i = 0; i < 4; i++)
        #pragma unroll
        for (int j = 0; j < 4; j++)
            #pragma unroll
            for (int r = 0; r < 4; r++) acc[i][j][r] = 0.f;

    const uint32_t a_row  = (uint32_t)(wm * 64 + (lane & 15));
    const uint32_t a_k8   = (uint32_t)(lane >> 4);
    const uint32_t b_row  = (uint32_t)(wn * 32 + (lane & 7) + ((lane >> 4) << 3));
    const uint32_t b_k8   = (uint32_t)((lane >> 3) & 1);

    const int NK = K / 32;
    issue_tile(sbase, Ahi, Alo, Bhi, Blo, m0, n0, 0, K, tid);
    CP_COMMIT();

    for (int kt = 0; kt < NK; kt++) {
        CP_WAIT0();
        __syncthreads();
        if (kt + 1 < NK) {
            issue_tile(sbase + (uint32_t)((kt + 1) & 1) * BUF_BYTES,
                       Ahi, Alo, Bhi, Blo, m0, n0, (kt + 1) * 32, K, tid);
            CP_COMMIT();
        }
        const uint32_t buf = sbase + (uint32_t)(kt & 1) * BUF_BYTES;

        #pragma unroll
        for (int ks = 0; ks < 2; ks++) {
            uint32_t ah[4][4], al[4][4], bh[2][4], bl[2][4];
            #pragma unroll
            for (int mb = 0; mb < 4; mb++) {
                uint32_t addr = buf + (a_row + mb * 16) * 80
                                    + (ks * 2 + a_k8) * 16;
                LDSM4(ah[mb], addr);
                LDSM4(al[mb], addr + TILE_BYTES);
            }
            #pragma unroll
            for (int nb = 0; nb < 2; nb++) {
                uint32_t addr = buf + 2*TILE_BYTES
                                    + (b_row + nb * 16) * 80
                                    + (ks * 2 + b_k8) * 16;
                LDSM4(bh[nb], addr);
                LDSM4(bl[nb], addr + TILE_BYTES);
            }
            #pragma unroll
            for (int mb = 0; mb < 4; mb++) {
                #pragma unroll
                for (int n8 = 0; n8 < 4; n8++) {
                    uint32_t* Bh = &bh[n8 >> 1][(n8 & 1) * 2];
                    uint32_t* Bl = &bl[n8 >> 1][(n8 & 1) * 2];
                    MMA_BF16(acc[mb][n8], ah[mb], Bh);
                    MMA_BF16(acc[mb][n8], ah[mb], Bl);
                    MMA_BF16(acc[mb][n8], al[mb], Bh);
                }
            }
        }
    }

    if (Ch) {
        // direct bf16 hi/lo split epilogue (for V projection)
        #pragma unroll
        for (int mb = 0; mb < 4; mb++) {
            int row = m0 + wm * 64 + mb * 16 + (lane >> 2);
            #pragma unroll
            for (int n8 = 0; n8 < 4; n8++) {
                int col = n0 + wn * 32 + n8 * 8 + (lane & 3) * 2;
                uint32_t ph, pl;
                pack_split(acc[mb][n8][0], acc[mb][n8][1], ph, pl);
                *reinterpret_cast<uint32_t*>(&Ch[(size_t)row * N + col]) = ph;
                *reinterpret_cast<uint32_t*>(&Cl[(size_t)row * N + col]) = pl;
                pack_split(acc[mb][n8][2], acc[mb][n8][3], ph, pl);
                *reinterpret_cast<uint32_t*>(&Ch[(size_t)(row + 8) * N + col]) = ph;
                *reinterpret_cast<uint32_t*>(&Cl[(size_t)(row + 8) * N + col]) = pl;
            }
        }
    } else {
        #pragma unroll
        for (int mb = 0; mb < 4; mb++) {
            int row = m0 + wm * 64 + mb * 16 + (lane >> 2);
            #pragma unroll
            for (int n8 = 0; n8 < 4; n8++) {
                int col = n0 + wn * 32 + n8 * 8 + (lane & 3) * 2;
                *reinterpret_cast<float2*>(&C[(size_t)row * N + col]) =
                    make_float2(acc[mb][n8][0], acc[mb][n8][1]);
                *reinterpret_cast<float2*>(&C[(size_t)(row + 8) * N + col]) =
                    make_float2(acc[mb][n8][2], acc[mb][n8][3]);
            }
        }
    }
}

__global__ __launch_bounds__(256) void gemm_mma(
    const __nv_bfloat16* __restrict__ Ahi, const __nv_bfloat16* __restrict__ Alo,
    const __nv_bfloat16* __restrict__ Bhi, const __nv_bfloat16* __restrict__ Blo,
    float* __restrict__ C, int M, int N, int K)
{
    extern __shared__ char sm[];
    gemm_body(smem_u32(sm), Ahi, Alo, Bhi, Blo, C, nullptr, nullptr,
              M, N, K, blockIdx.y * 128, blockIdx.x * 128);
}

// combined Q/K/V projections; V writes bf16 hi/lo directly
__global__ __launch_bounds__(256) void gemm_mma_qkv(
    const __nv_bfloat16* __restrict__ Ahi, const __nv_bfloat16* __restrict__ Alo,
    const __nv_bfloat16* __restrict__ Wqh, const __nv_bfloat16* __restrict__ Wql,
    const __nv_bfloat16* __restrict__ Wkh, const __nv_bfloat16* __restrict__ Wkl,
    const __nv_bfloat16* __restrict__ Wvh, const __nv_bfloat16* __restrict__ Wvl,
    float* __restrict__ Cq, float* __restrict__ Ck,
    __nv_bfloat16* __restrict__ Vh, __nv_bfloat16* __restrict__ Vl)
{
    extern __shared__ char sm[];
    int bx = blockIdx.x;
    if (bx < 8) {
        gemm_body(smem_u32(sm), Ahi, Alo, Wqh, Wql, Cq, nullptr, nullptr,
                  MM, EE, EE, blockIdx.y * 128, bx * 128);
    } else if (bx < 10) {
        gemm_body(smem_u32(sm), Ahi, Alo, Wkh, Wkl, Ck, nullptr, nullptr,
                  MM, KVH * HD, EE, blockIdx.y * 128, (bx - 8) * 128);
    } else {
        gemm_body(smem_u32(sm), Ahi, Alo, Wvh, Wvl, nullptr, Vh, Vl,
                  MM, KVH * HD, EE, blockIdx.y * 128, (bx - 10) * 128);
    }
}

// ---------------------------------------------------------------------------
// Flash attention, 1 head/CTA, bf16 hi/lo split, BM=BN=64, 4 warps, 3 CTAs/SM.
// Q RoPE fused into prologue (reads fp32 q + cos/sin).
// Prologue scratch (fp32 q stage + QH/QL) overlays KV buffer 1.
// ---------------------------------------------------------------------------
#define FROW      144
#define FARR      (64*FROW)            // 9216
#define KVBUF     (4*FARR)             // 36864: kh, kl, vh, vl
#define OFF_KH    0
#define OFF_KL    FARR
#define OFF_VH    (2*FARR)
#define OFF_VL    (3*FARR)
// prologue-only regions inside KV buffer 1:
#define QSTAGE    KVBUF                // fp32 q tile, rows padded to 272B
#define QSROW     272                  // 64*272 = 17408
#define SM_QH     (KVBUF + 17408)      // bf16 hi; lo at +FARR (72704 <= 73728)
#define FLASH_SMEM (8*FARR)            // 73728; 3 CTAs/SM

#define SCALE_L2E 0.180336879f         // 0.125 * log2(e)

__device__ __forceinline__ void flash_load_kv(
    uint32_t kb,
    const __nv_bfloat16* __restrict__ kh, const __nv_bfloat16* __restrict__ kl,
    const __nv_bfloat16* __restrict__ vh, const __nv_bfloat16* __restrict__ vl,
    int b, int kt, int kvh, int tid)
{
    #pragma unroll
    for (int it = 0; it < 4; it++) {
        int idx = tid + it * 128;
        int r   = idx >> 3;
        int c   = idx & 7;
        size_t g = (size_t)(b * TT + kt * 64 + r) * (KVH * HD) + kvh * 64 + c * 8;
        uint32_t so = (uint32_t)(r * FROW + c * 16);
        CP_ASYNC16(kb + OFF_KH + so, (const char*)(kh + g));
        CP_ASYNC16(kb + OFF_KL + so, (const char*)(kl + g));
        CP_ASYNC16(kb + OFF_VH + so, (const char*)(vh + g));
        CP_ASYNC16(kb + OFF_VL + so, (const char*)(vl + g));
    }
}

__global__ __launch_bounds__(128, 3) void flash_mma(
    const float* __restrict__ qf,
    const float* __restrict__ cs, const float* __restrict__ sn,
    const __nv_bfloat16* __restrict__ kh, const __nv_bfloat16* __restrict__ kl,
    const __nv_bfloat16* __restrict__ vh, const __nv_bfloat16* __restrict__ vl,
    __nv_bfloat16* __restrict__ yh, __nv_bfloat16* __restrict__ yl)
{
    extern __shared__ char sm[];
    const uint32_t sb = smem_u32(sm);
    const int tid  = threadIdx.x;
    const int lane = tid & 31;
    const int wid  = tid >> 5;
    const int qt   = (int)(gridDim.x - 1 - blockIdx.x);   // big tiles first
    const int h    = blockIdx.y;
    const int b    = blockIdx.z;
    const int kvh  = h / GG;

    // --- prologue: stage fp32 q tile; prefetch KV tile 0 ---
    #pragma unroll
    for (int it = 0; it < 8; it++) {
        int idx = tid + it * 128;      // 0..1023 16B-chunks (64 rows x 16)
        int r   = idx >> 4;
        int c   = idx & 15;
        size_t g = (size_t)(b * TT + qt * 64 + r) * EE + h * 64 + c * 4;
        CP_ASYNC16(sb + QSTAGE + r * QSROW + c * 16, (const char*)(qf + g));
    }
    CP_COMMIT();
    flash_load_kv(sb, kh, kl, vh, vl, b, 0, kvh, tid);
    CP_COMMIT();

    CP_WAIT1();          // q stage complete
    __syncthreads();

    // --- RoPE q in-CTA, write bf16 hi/lo to QH/QL smem ---
    {
        int r  = tid >> 1;
        int s2 = tid & 1;
        const float* qs = reinterpret_cast<const float*>(sm + QSTAGE + r * QSROW);
        size_t crow = (size_t)(b * TT + qt * 64 + r) * 64;
        __nv_bfloat16* qhr = reinterpret_cast<__nv_bfloat16*>(sm + SM_QH + r * FROW);
        __nv_bfloat16* qlr = reinterpret_cast<__nv_bfloat16*>(sm + SM_QH + FARR + r * FROW);
        #pragma unroll
        for (int i = 0; i < 16; i++) {
            int d = s2 * 16 + i;
            float x1 = qs[d], x2 = qs[d + 32];
            float y1 = x1 * cs[crow + d]      - x2 * sn[crow + d];
            float y2 = x2 * cs[crow + d + 32] + x1 * sn[crow + d + 32];
            __nv_bfloat16 h1 = __float2bfloat16(y1);
            __nv_bfloat16 h2 = __float2bfloat16(y2);
            qhr[d]      = h1;
            qhr[d + 32] = h2;
            qlr[d]      = __float2bfloat16(y1 - __bfloat162float(h1));
            qlr[d + 32] = __float2bfloat16(y2 - __bfloat162float(h2));
        }
    }
    __syncthreads();

    // Q A-fragments resident
    uint32_t qfh[4][4], qfl[4][4];
    {
        const uint32_t a_row = (uint32_t)(wid * 16 + (lane & 15));
        const uint32_t a_k8  = (uint32_t)(lane >> 4);
        #pragma unroll
        for (int ks = 0; ks < 4; ks++) {
            uint32_t addr = sb + SM_QH + a_row * FROW + (ks * 2 + a_k8) * 16;
            LDSM4(qfh[ks], addr);
            LDSM4(qfl[ks], addr + FARR);
        }
    }
    __syncthreads();     // buffer-1 region free for prefetch after this

    const uint32_t kb_row = (uint32_t)((lane & 7) + ((lane >> 4) << 3));
    const uint32_t kb_k8  = (uint32_t)((lane >> 3) & 1);
    const uint32_t vb_row = (uint32_t)((lane & 7) + (((lane >> 3) & 1) << 3));
    const uint32_t vb_col = (uint32_t)((lane >> 4) << 3);

    float oacc[8][4];
    #pragma unroll
    for (int nb = 0; nb < 8; nb++)
        #pragma unroll
        for (int j = 0; j < 4; j++) oacc[nb][j] = 0.f;
    float m0 = -INFINITY, m1 = -INFINITY, l0 = 0.f, l1 = 0.f;

    int cur = 0;
    for (int kt = 0; kt <= qt; kt++) {
        if (kt + 1 <= qt) {
            flash_load_kv(sb + (uint32_t)(cur ^ 1) * KVBUF,
                          kh, kl, vh, vl, b, kt + 1, kvh, tid);
            CP_COMMIT();
            CP_WAIT1();
        } else {
            CP_WAIT0();
        }
        __syncthreads();
        const uint32_t kvb = sb + (uint32_t)cur * KVBUF;
        const bool diag = (kt == qt);

        // ---- S = Q K^T (3-term split), fully unrolled, uniform diag skip ----
        float sacc[8][4];
        #pragma unroll
        for (int nb = 0; nb < 8; nb++)
            #pragma unroll
            for (int j = 0; j < 4; j++) sacc[nb][j] = 0.f;

        #pragma unroll
        for (int ks = 0; ks < 4; ks++) {
            #pragma unroll
            for (int nb = 0; nb < 4; nb++) {
                if (diag && nb > wid) continue;
                uint32_t addr = kvb + OFF_KH + (kb_row + nb * 16) * FROW
                                            + (ks * 2 + kb_k8) * 16;
                uint32_t bh[4], bl[4];
                LDSM4(bh, addr);
                LDSM4(bl, addr + FARR);
                MMA_BF16(sacc[2*nb],   qfh[ks], bh);
                MMA_BF16(sacc[2*nb],   qfh[ks], bl);
                MMA_BF16(sacc[2*nb],   qfl[ks], bh);
                MMA_BF16(sacc[2*nb+1], qfh[ks], bh + 2);
                MMA_BF16(sacc[2*nb+1], qfh[ks], bl + 2);
                MMA_BF16(sacc[2*nb+1], qfl[ks], bh + 2);
            }
        }

        // ---- scale (base-2) + causal mask ----
        #pragma unroll
        for (int nb = 0; nb < 8; nb++)
            #pragma unroll
            for (int j = 0; j < 4; j++) sacc[nb][j] *= SCALE_L2E;
        if (diag) {
            #pragma unroll
            for (int nb = 0; nb < 8; nb++)
                #pragma unroll
                for (int j = 0; j < 4; j++) {
                    int n_loc = nb * 8 + 2 * (lane & 3) + (j & 1);
                    int m_loc = wid * 16 + (lane >> 2) + ((j >> 1) << 3);
                    if (n_loc > m_loc) sacc[nb][j] = -1e30f;
                }
        }

        // ---- online softmax (base-2) ----
        float mx0 = -INFINITY, mx1 = -INFINITY;
        #pragma unroll
        for (int nb = 0; nb < 8; nb++) {
            mx0 = fmaxf(mx0, fmaxf(sacc[nb][0], sacc[nb][1]));
            mx1 = fmaxf(mx1, fmaxf(sacc[nb][2], sacc[nb][3]));
        }
        mx0 = fmaxf(mx0, __shfl_xor_sync(0xffffffffu, mx0, 1));
        mx0 = fmaxf(mx0, __shfl_xor_sync(0xffffffffu, mx0, 2));
        mx1 = fmaxf(mx1, __shfl_xor_sync(0xffffffffu, mx1, 1));
        mx1 = fmaxf(mx1, __shfl_xor_sync(0xffffffffu, mx1, 2));

        float mn0 = fmaxf(m0, mx0), mn1 = fmaxf(m1, mx1);
        float al0 = exp2f(m0 - mn0), al1 = exp2f(m1 - mn1);
        m0 = mn0; m1 = mn1;

        float sum0 = 0.f, sum1 = 0.f;
        #pragma unroll
        for (int nb = 0; nb < 8; nb++) {
            sacc[nb][0] = exp2f(sacc[nb][0] - mn0);
            sacc[nb][1] = exp2f(sacc[nb][1] - mn0);
            sacc[nb][2] = exp2f(sacc[nb][2] - mn1);
            sacc[nb][3] = exp2f(sacc[nb][3] - mn1);
            sum0 += sacc[nb][0] + sacc[nb][1];
            sum1 += sacc[nb][2] + sacc[nb][3];
        }
        sum0 += __shfl_xor_sync(0xffffffffu, sum0, 1);
        sum0 += __shfl_xor_sync(0xffffffffu, sum0, 2);
        sum1 += __shfl_xor_sync(0xffffffffu, sum1, 1);
        sum1 += __shfl_xor_sync(0xffffffffu, sum1, 2);
        l0 = l0 * al0 + sum0;
        l1 = l1 * al1 + sum1;

        #pragma unroll
        for (int nb = 0; nb < 8; nb++) {
            oacc[nb][0] *= al0; oacc[nb][1] *= al0;
            oacc[nb][2] *= al1; oacc[nb][3] *= al1;
        }

        // ---- streamed pack + PV ----
        #pragma unroll
        for (int j16 = 0; j16 < 4; j16++) {
            if (diag && j16 > wid) continue;        // P block is all zeros
            uint32_t pfh[4], pfl[4];
            {
                float* c0 = sacc[2*j16];
                float* c1 = sacc[2*j16 + 1];
                #pragma unroll
                for (int a = 0; a < 4; a++) {
                    float v0 = (a < 2) ? c0[(a & 1) * 2]     : c1[(a & 1) * 2];
                    float v1 = (a < 2) ? c0[(a & 1) * 2 + 1] : c1[(a & 1) * 2 + 1];
                    pack_split(v0, v1, pfh[a], pfl[a]);
                }
            }
            #pragma unroll
            for (int nb = 0; nb < 4; nb++) {
                uint32_t addr = kvb + OFF_VH
                              + (j16 * 16 + vb_row) * FROW
                              + (nb * 16 + vb_col) * 2;
                uint32_t vhf[4], vlf[4];
                LDSM4T(vhf, addr);
                LDSM4T(vlf, addr + FARR);
                MMA_BF16(oacc[2*nb],   pfh, vhf);
                MMA_BF16(oacc[2*nb],   pfh, vlf);
                MMA_BF16(oacc[2*nb],   pfl, vhf);
                MMA_BF16(oacc[2*nb+1], pfh, vhf + 2);
                MMA_BF16(oacc[2*nb+1], pfh, vlf + 2);
                MMA_BF16(oacc[2*nb+1], pfl, vhf + 2);
            }
        }

        __syncthreads();
        cur ^= 1;
    }

    // ---- epilogue: normalize, split to bf16 hi/lo, store directly ----
    float inv0 = 1.f / l0, inv1 = 1.f / l1;
    size_t row0 = (size_t)(b * TT + qt * 64 + wid * 16 + (lane >> 2));
    #pragma unroll
    for (int nb = 0; nb < 8; nb++) {
        size_t col = (size_t)(h * 64 + nb * 8 + 2 * (lane & 3));
        uint32_t ph, pl;
        pack_split(oacc[nb][0] * inv0, oacc[nb][1] * inv0, ph, pl);
        *reinterpret_cast<uint32_t*>(&yh[row0 * EE + col]) = ph;
        *reinterpret_cast<uint32_t*>(&yl[row0 * EE + col]) = pl;
        pack_split(oacc[nb][2] * inv1, oacc[nb][3] * inv1, ph, pl);
        *reinterpret_cast<uint32_t*>(&yh[(row0 + 8) * EE + col]) = ph;
        *reinterpret_cast<uint32_t*>(&yl[(row0 + 8) * EE + col]) = pl;
    }
}

// ---------------------------------------------------------------------------
// kernel_launch — 5 launches; flash_mma is #4 (profiler window)
// ---------------------------------------------------------------------------
extern "C" void kernel_launch(void* const* d_in, const int* in_sizes, int n_in,
                              void* d_out, int out_size)
{
    const float* x   = (const float*)d_in[0];
    const float* cs  = (const float*)d_in[1];
    const float* sn  = (const float*)d_in[2];
    const float* Wq  = (const float*)d_in[3];
    const float* Wk  = (const float*)d_in[4];
    const float* Wv  = (const float*)d_in[5];
    const float* Wo  = (const float*)d_in[6];
    float* out = (float*)d_out;

    float *q, *k;
    cudaGetSymbolAddress((void**)&q, g_q);
    cudaGetSymbolAddress((void**)&k, g_k);

    __nv_bfloat16 *xh, *xl, *yh, *yl;
    __nv_bfloat16 *wqh, *wql, *wkh, *wkl, *wvh, *wvl, *woh, *wol;
    __nv_bfloat16 *khp, *klp, *vhp, *vlp;
    cudaGetSymbolAddress((void**)&xh,  g_x_hi);  cudaGetSymbolAddress((void**)&xl,  g_x_lo);
    cudaGetSymbolAddress((void**)&yh,  g_y_hi);  cudaGetSymbolAddress((void**)&yl,  g_y_lo);
    cudaGetSymbolAddress((void**)&wqh, g_wq_hi); cudaGetSymbolAddress((void**)&wql, g_wq_lo);
    cudaGetSymbolAddress((void**)&wkh, g_wk_hi); cudaGetSymbolAddress((void**)&wkl, g_wk_lo);
    cudaGetSymbolAddress((void**)&wvh, g_wv_hi); cudaGetSymbolAddress((void**)&wvl, g_wv_lo);
    cudaGetSymbolAddress((void**)&woh, g_wo_hi); cudaGetSymbolAddress((void**)&wol, g_wo_lo);
    cudaGetSymbolAddress((void**)&khp, g_kh);    cudaGetSymbolAddress((void**)&klp, g_kl);
    cudaGetSymbolAddress((void**)&vhp, g_vh);    cudaGetSymbolAddress((void**)&vlp, g_vl);

    cudaFuncSetAttribute(gemm_mma, cudaFuncAttributeMaxDynamicSharedMemorySize,
                         GEMM_SMEM);
    cudaFuncSetAttribute(gemm_mma_qkv, cudaFuncAttributeMaxDynamicSharedMemorySize,
                         GEMM_SMEM);
    cudaFuncSetAttribute(flash_mma, cudaFuncAttributeMaxDynamicSharedMemorySize,
                         FLASH_SMEM);

    // #1: all input splits
    {
        SplitArgs a;
        a.in[0] = x;  a.hi[0] = xh;  a.lo[0] = xl;  a.n4[0] = MM * EE / 4;
        a.in[1] = Wq; a.hi[1] = wqh; a.lo[1] = wql; a.n4[1] = EE * EE / 4;
        a.in[2] = Wk; a.hi[2] = wkh; a.lo[2] = wkl; a.n4[2] = KVH * HD * EE / 4;
        a.in[3] = Wv; a.hi[3] = wvh; a.lo[3] = wvl; a.n4[3] = KVH * HD * EE / 4;
        a.in[4] = Wo; a.hi[4] = woh; a.lo[4] = wol; a.n4[4] = EE * EE / 4;
        int maxb = (MM * EE / 4 + 255) / 256;
        split_all<<<dim3(maxb, 5), 256>>>(a);
    }

    // #2: Q + K + V projections (V emits bf16 hi/lo directly)
    gemm_mma_qkv<<<dim3(12, MM / 128), 256, GEMM_SMEM>>>(
        xh, xl, wqh, wql, wkh, wkl, wvh, wvl, q, k, vhp, vlp);

    // #3: k rope + split
    {
        int n = BB * TT * KVH * 32;
        rope_k<<<(n + 255) / 256, 256>>>(k, cs, sn, khp, klp);
    }

    // #4: flash attention (q rope fused; writes yh/yl) — profiler window
    flash_mma<<<dim3(TT / 64, HH, BB), 128, FLASH_SMEM>>>(
        q, cs, sn, khp, klp, vhp, vlp, yh, yl);

    // #5: output projection
    gemm_mma<<<dim3(EE / 128, MM / 128), 256, GEMM_SMEM>>>(yh, yl, woh, wol, out, MM, EE, EE);
}

// round 11
// speedup vs baseline: 1.0982x; 1.0190x over previous
#include <cuda_runtime.h>
#include <cuda_bf16.h>
#include <math.h>
#include <stdint.h>

// Problem constants
#define BB 2
#define TT 2048
#define EE 1024
#define HH 16
#define KVH 4
#define HD 64
#define GG 4           // H / KVH
#define MM (BB*TT)     // 4096 rows

// ---------------------------------------------------------------------------
// Device scratch (allocation-free rule: __device__ globals)
// ---------------------------------------------------------------------------
__device__ float g_q[MM*EE];            // fp32 q (rope fused into flash)
__device__ float g_k[MM*KVH*HD];        // fp32 k (rope_k reads)

__device__ __nv_bfloat16 g_x_hi[MM*EE],      g_x_lo[MM*EE];
__device__ __nv_bfloat16 g_y_hi[MM*EE],      g_y_lo[MM*EE];
__device__ __nv_bfloat16 g_wq_hi[EE*EE],     g_wq_lo[EE*EE];
__device__ __nv_bfloat16 g_wk_hi[KVH*HD*EE], g_wk_lo[KVH*HD*EE];
__device__ __nv_bfloat16 g_wv_hi[KVH*HD*EE], g_wv_lo[KVH*HD*EE];
__device__ __nv_bfloat16 g_wo_hi[EE*EE],     g_wo_lo[EE*EE];

__device__ __nv_bfloat16 g_kh[MM*KVH*HD],    g_kl[MM*KVH*HD];
__device__ __nv_bfloat16 g_vh[MM*KVH*HD],    g_vl[MM*KVH*HD];

// ---------------------------------------------------------------------------
// PTX helpers
// ---------------------------------------------------------------------------
__device__ __forceinline__ uint32_t smem_u32(const void* p) {
    uint32_t a;
    asm("{ .reg .u64 t; cvta.to.shared.u64 t, %1; cvt.u32.u64 %0, t; }"
        : "=r"(a) : "l"(p));
    return a;
}

#define LDSM4(r, addr) \
    asm volatile("ldmatrix.sync.aligned.m8n8.x4.shared.b16 {%0,%1,%2,%3}, [%4];" \
        : "=r"((r)[0]), "=r"((r)[1]), "=r"((r)[2]), "=r"((r)[3]) : "r"(addr))

#define LDSM4T(r, addr) \
    asm volatile("ldmatrix.sync.aligned.m8n8.x4.trans.shared.b16 {%0,%1,%2,%3}, [%4];" \
        : "=r"((r)[0]), "=r"((r)[1]), "=r"((r)[2]), "=r"((r)[3]) : "r"(addr))

#define MMA_BF16(d, a, b) \
    asm volatile("mma.sync.aligned.m16n8k16.row.col.f32.bf16.bf16.f32 " \
        "{%0,%1,%2,%3}, {%4,%5,%6,%7}, {%8,%9}, {%0,%1,%2,%3};" \
        : "+f"((d)[0]), "+f"((d)[1]), "+f"((d)[2]), "+f"((d)[3]) \
        : "r"((a)[0]), "r"((a)[1]), "r"((a)[2]), "r"((a)[3]), \
          "r"((b)[0]), "r"((b)[1]))

#define CP_ASYNC16(dst, src) \
    asm volatile("cp.async.cg.shared.global [%0], [%1], 16;" \
        :: "r"(dst), "l"(src))
#define CP_COMMIT() asm volatile("cp.async.commit_group;" ::: "memory")
#define CP_WAIT0()  asm volatile("cp.async.wait_group 0;" ::: "memory")
#define CP_WAIT1()  asm volatile("cp.async.wait_group 1;" ::: "memory")

__device__ __forceinline__ uint32_t pack_bf16(float lo, float hi) {
    __nv_bfloat162 t = __float22bfloat162_rn(make_float2(lo, hi));
    return *reinterpret_cast<uint32_t*>(&t);
}

// pack to bf16x2 and also produce the residual pair using the packed halves
__device__ __forceinline__ void pack_split(float v0, float v1,
                                           uint32_t& ph, uint32_t& pl) {
    ph = pack_bf16(v0, v1);
    __nv_bfloat162 hb = *reinterpret_cast<__nv_bfloat162*>(&ph);
    pl = pack_bf16(v0 - __bfloat162float(hb.x), v1 - __bfloat162float(hb.y));
}

// ---------------------------------------------------------------------------
// Batched split (x + 4 weights)
// ---------------------------------------------------------------------------
struct SplitArgs {
    const float*   in[5];
    __nv_bfloat16* hi[5];
    __nv_bfloat16* lo[5];
    int            n4[5];
};

__device__ __forceinline__ void split_one(const float* __restrict__ in,
                                          __nv_bfloat16* __restrict__ hi,
                                          __nv_bfloat16* __restrict__ lo, int i)
{
    float4 v = reinterpret_cast<const float4*>(in)[i];
    uint32_t ph0, pl0, ph1, pl1;
    pack_split(v.x, v.y, ph0, pl0);
    pack_split(v.z, v.w, ph1, pl1);
    reinterpret_cast<uint2*>(hi)[i] = make_uint2(ph0, ph1);
    reinterpret_cast<uint2*>(lo)[i] = make_uint2(pl0, pl1);
}

__global__ void split_all(SplitArgs a)
{
    int seg = blockIdx.y;
    int i   = blockIdx.x * blockDim.x + threadIdx.x;
    if (i >= a.n4[seg]) return;
    split_one(a.in[seg], a.hi[seg], a.lo[seg], i);
}

// ---------------------------------------------------------------------------
// rope_k: k rope + split only
// ---------------------------------------------------------------------------
__global__ void rope_k(const float* __restrict__ k,
                       const float* __restrict__ c,
                       const float* __restrict__ s,
                       __nv_bfloat16* __restrict__ kh,
                       __nv_bfloat16* __restrict__ kl)
{
    int idx = blockIdx.x * blockDim.x + threadIdx.x;
    int n = BB * TT * KVH * 32;
    if (idx >= n) return;

    int d  = idx & 31;
    int r  = idx >> 5;
    int h  = r % KVH;
    int bt = r / KVH;

    const float* p  = k + ((size_t)bt * KVH + h) * 64;
    const float* cp = c + (size_t)bt * 64;
    const float* sp = s + (size_t)bt * 64;

    float x1 = p[d];
    float x2 = p[d + 32];
    float y1 = x1 * cp[d]      - x2 * sp[d];
    float y2 = x2 * cp[d + 32] + x1 * sp[d + 32];

    size_t o = ((size_t)bt * KVH + h) * 64;
    __nv_bfloat16 h1 = __float2bfloat16(y1);
    __nv_bfloat16 h2 = __float2bfloat16(y2);
    kh[o + d]      = h1;
    kh[o + d + 32] = h2;
    kl[o + d]      = __float2bfloat16(y1 - __bfloat162float(h1));
    kl[o + d + 32] = __float2bfloat16(y2 - __bfloat162float(h2));
}

// ---------------------------------------------------------------------------
// mma.sync GEMM body: C = A * W^T, bf16x2 split (hh+hl+lh).
// Epilogue: fp32 C OR direct bf16 hi/lo split (Ch/Cl) when Ch != nullptr.
// ---------------------------------------------------------------------------
#define TILE_BYTES   10240
#define BUF_BYTES    (4*TILE_BYTES)
#define GEMM_SMEM    (2*BUF_BYTES)

__device__ __forceinline__ void issue_tile(
    uint32_t sbuf,
    const __nv_bfloat16* __restrict__ Ahi, const __nv_bfloat16* __restrict__ Alo,
    const __nv_bfloat16* __restrict__ Bhi, const __nv_bfloat16* __restrict__ Blo,
    int m0, int n0, int k0, int K, int tid)
{
    #pragma unroll
    for (int it = 0; it < 2; it++) {
        int idx = tid + it * 256;
        int r   = idx >> 2;
        int c8  = idx & 3;
        uint32_t so = (uint32_t)(r * 80 + c8 * 16);
        size_t ga = (size_t)(m0 + r) * K + k0 + c8 * 8;
        size_t gb = (size_t)(n0 + r) * K + k0 + c8 * 8;
        CP_ASYNC16(sbuf + so,                 (const char*)(Ahi + ga));
        CP_ASYNC16(sbuf + TILE_BYTES + so,    (const char*)(Alo + ga));
        CP_ASYNC16(sbuf + 2*TILE_BYTES + so,  (const char*)(Bhi + gb));
        CP_ASYNC16(sbuf + 3*TILE_BYTES + so,  (const char*)(Blo + gb));
    }
}

__device__ __forceinline__ void gemm_body(
    uint32_t sbase,
    const __nv_bfloat16* __restrict__ Ahi, const __nv_bfloat16* __restrict__ Alo,
    const __nv_bfloat16* __restrict__ Bhi, const __nv_bfloat16* __restrict__ Blo,
    float* __restrict__ C,
    __nv_bfloat16* __restrict__ Ch, __nv_bfloat16* __restrict__ Cl,
    int M, int N, int K, int m0, int n0)
{
    const int tid  = threadIdx.x;
    const int lane = tid & 31;
    const int wid  = tid >> 5;
    const int wm   = wid >> 2;
    const int wn   = wid & 3;

    float acc[4][4][4];
    #pragma unroll
    for (int i = 0; i < 4; i++)
        #pragma unroll
        for (int j = 0; j < 4; j++)
            #pragma unroll
            for (int r = 0; r < 4; r++) acc[i][j][r] = 0.f;

    const uint32_t a_row  = (uint32_t)(wm * 64 + (lane & 15));
    const uint32_t a_k8   = (uint32_t)(lane >> 4);
    const uint32_t b_row  = (uint32_t)(wn * 32 + (lane & 7) + ((lane >> 4) << 3));
    const uint32_t b_k8   = (uint32_t)((lane >> 3) & 1);

    const int NK = K / 32;
    issue_tile(sbase, Ahi, Alo, Bhi, Blo, m0, n0, 0, K, tid);
    CP_COMMIT();

    for (int kt = 0; kt < NK; kt++) {
        CP_WAIT0();
        __syncthreads();
        if (kt + 1 < NK) {
            issue_tile(sbase + (uint32_t)((kt + 1) & 1) * BUF_BYTES,
                       Ahi, Alo, Bhi, Blo, m0, n0, (kt + 1) * 32, K, tid);
            CP_COMMIT();
        }
        const uint32_t buf = sbase + (uint32_t)(kt & 1) * BUF_BYTES;

        #pragma unroll
        for (int ks = 0; ks < 2; ks++) {
            uint32_t ah[4][4], al[4][4], bh[2][4], bl[2][4];
            #pragma unroll
            for (int mb = 0; mb < 4; mb++) {
                uint32_t addr = buf + (a_row + mb * 16) * 80
                                    + (ks * 2 + a_k8) * 16;
                LDSM4(ah[mb], addr);
                LDSM4(al[mb], addr + TILE_BYTES);
            }
            #pragma unroll
            for (int nb = 0; nb < 2; nb++) {
                uint32_t addr = buf + 2*TILE_BYTES
                                    + (b_row + nb * 16) * 80
                                    + (ks * 2 + b_k8) * 16;
                LDSM4(bh[nb], addr);
                LDSM4(bl[nb], addr + TILE_BYTES);
            }
            #pragma unroll
            for (int mb = 0; mb < 4; mb++) {
                #pragma unroll
                for (int n8 = 0; n8 < 4; n8++) {
                    uint32_t* Bh = &bh[n8 >> 1][(n8 & 1) * 2];
                    uint32_t* Bl = &bl[n8 >> 1][(n8 & 1) * 2];
                    MMA_BF16(acc[mb][n8], ah[mb], Bh);
                    MMA_BF16(acc[mb][n8], ah[mb], Bl);
                    MMA_BF16(acc[mb][n8], al[mb], Bh);
                }
            }
        }
    }

    if (Ch) {
        #pragma unroll
        for (int mb = 0; mb < 4; mb++) {
            int row = m0 + wm * 64 + mb * 16 + (lane >> 2);
            #pragma unroll
            for (int n8 = 0; n8 < 4; n8++) {
                int col = n0 + wn * 32 + n8 * 8 + (lane & 3) * 2;
                uint32_t ph, pl;
                pack_split(acc[mb][n8][0], acc[mb][n8][1], ph, pl);
                *reinterpret_cast<uint32_t*>(&Ch[(size_t)row * N + col]) = ph;
                *reinterpret_cast<uint32_t*>(&Cl[(size_t)row * N + col]) = pl;
                pack_split(acc[mb][n8][2], acc[mb][n8][3], ph, pl);
                *reinterpret_cast<uint32_t*>(&Ch[(size_t)(row + 8) * N + col]) = ph;
                *reinterpret_cast<uint32_t*>(&Cl[(size_t)(row + 8) * N + col]) = pl;
            }
        }
    } else {
        #pragma unroll
        for (int mb = 0; mb < 4; mb++) {
            int row = m0 + wm * 64 + mb * 16 + (lane >> 2);
            #pragma unroll
            for (int n8 = 0; n8 < 4; n8++) {
                int col = n0 + wn * 32 + n8 * 8 + (lane & 3) * 2;
                *reinterpret_cast<float2*>(&C[(size_t)row * N + col]) =
                    make_float2(acc[mb][n8][0], acc[mb][n8][1]);
                *reinterpret_cast<float2*>(&C[(size_t)(row + 8) * N + col]) =
                    make_float2(acc[mb][n8][2], acc[mb][n8][3]);
            }
        }
    }
}

__global__ __launch_bounds__(256) void gemm_mma(
    const __nv_bfloat16* __restrict__ Ahi, const __nv_bfloat16* __restrict__ Alo,
    const __nv_bfloat16* __restrict__ Bhi, const __nv_bfloat16* __restrict__ Blo,
    float* __restrict__ C, int M, int N, int K)
{
    extern __shared__ char sm[];
    gemm_body(smem_u32(sm), Ahi, Alo, Bhi, Blo, C, nullptr, nullptr,
              M, N, K, blockIdx.y * 128, blockIdx.x * 128);
}

// combined Q/K/V projections; V writes bf16 hi/lo directly
__global__ __launch_bounds__(256) void gemm_mma_qkv(
    const __nv_bfloat16* __restrict__ Ahi, const __nv_bfloat16* __restrict__ Alo,
    const __nv_bfloat16* __restrict__ Wqh, const __nv_bfloat16* __restrict__ Wql,
    const __nv_bfloat16* __restrict__ Wkh, const __nv_bfloat16* __restrict__ Wkl,
    const __nv_bfloat16* __restrict__ Wvh, const __nv_bfloat16* __restrict__ Wvl,
    float* __restrict__ Cq, float* __restrict__ Ck,
    __nv_bfloat16* __restrict__ Vh, __nv_bfloat16* __restrict__ Vl)
{
    extern __shared__ char sm[];
    int bx = blockIdx.x;
    if (bx < 8) {
        gemm_body(smem_u32(sm), Ahi, Alo, Wqh, Wql, Cq, nullptr, nullptr,
                  MM, EE, EE, blockIdx.y * 128, bx * 128);
    } else if (bx < 10) {
        gemm_body(smem_u32(sm), Ahi, Alo, Wkh, Wkl, Ck, nullptr, nullptr,
                  MM, KVH * HD, EE, blockIdx.y * 128, (bx - 8) * 128);
    } else {
        gemm_body(smem_u32(sm), Ahi, Alo, Wvh, Wvl, nullptr, Vh, Vl,
                  MM, KVH * HD, EE, blockIdx.y * 128, (bx - 10) * 128);
    }
}

// ---------------------------------------------------------------------------
// Flash attention, 1 head/CTA, bf16 hi/lo split, BM=BN=64, 4 warps, 3 CTAs/SM.
// Q RoPE fused: vectorized register rope (no fp32 smem stage).
// Q bf16 hi/lo overlays KV buffer 1 (dead before buffer 1's first prefetch).
// ---------------------------------------------------------------------------
#define FROW      144
#define FARR      (64*FROW)            // 9216
#define KVBUF     (4*FARR)             // 36864: kh, kl, vh, vl
#define OFF_KH    0
#define OFF_KL    FARR
#define OFF_VH    (2*FARR)
#define OFF_VL    (3*FARR)
#define SM_QH     KVBUF                // bf16 hi; lo at +FARR (within buffer 1)
#define FLASH_SMEM (8*FARR)            // 73728; 3 CTAs/SM

#define SCALE_L2E 0.180336879f         // 0.125 * log2(e)

__device__ __forceinline__ void flash_load_kv(
    uint32_t kb,
    const __nv_bfloat16* __restrict__ kh, const __nv_bfloat16* __restrict__ kl,
    const __nv_bfloat16* __restrict__ vh, const __nv_bfloat16* __restrict__ vl,
    int b, int kt, int kvh, int tid)
{
    #pragma unroll
    for (int it = 0; it < 4; it++) {
        int idx = tid + it * 128;
        int r   = idx >> 3;
        int c   = idx & 7;
        size_t g = (size_t)(b * TT + kt * 64 + r) * (KVH * HD) + kvh * 64 + c * 8;
        uint32_t so = (uint32_t)(r * FROW + c * 16);
        CP_ASYNC16(kb + OFF_KH + so, (const char*)(kh + g));
        CP_ASYNC16(kb + OFF_KL + so, (const char*)(kl + g));
        CP_ASYNC16(kb + OFF_VH + so, (const char*)(vh + g));
        CP_ASYNC16(kb + OFF_VL + so, (const char*)(vl + g));
    }
}

__global__ __launch_bounds__(128, 3) void flash_mma(
    const float* __restrict__ qf,
    const float* __restrict__ cs, const float* __restrict__ sn,
    const __nv_bfloat16* __restrict__ kh, const __nv_bfloat16* __restrict__ kl,
    const __nv_bfloat16* __restrict__ vh, const __nv_bfloat16* __restrict__ vl,
    __nv_bfloat16* __restrict__ yh, __nv_bfloat16* __restrict__ yl)
{
    extern __shared__ char sm[];
    const uint32_t sb = smem_u32(sm);
    const int tid  = threadIdx.x;
    const int lane = tid & 31;
    const int wid  = tid >> 5;
    const int qt   = (int)(gridDim.x - 1 - blockIdx.x);   // big tiles first
    const int h    = blockIdx.y;
    const int b    = blockIdx.z;
    const int kvh  = h / GG;

    // --- prefetch KV tile 0 immediately; rope overlaps the flight ---
    flash_load_kv(sb, kh, kl, vh, vl, b, 0, kvh, tid);
    CP_COMMIT();

    // --- Q RoPE in registers: thread handles row r = tid>>1, half s2 = tid&1 ---
    {
        int r  = tid >> 1;
        int s2 = tid & 1;
        size_t qrow = (size_t)(b * TT + qt * 64 + r) * EE + h * 64 + s2 * 16;
        size_t crow = (size_t)(b * TT + qt * 64 + r) * 64 + s2 * 16;
        float4 x1v[4], x2v[4], c1v[4], c2v[4], s1v[4], s2v[4];
        #pragma unroll
        for (int j = 0; j < 4; j++) {
            x1v[j] = *reinterpret_cast<const float4*>(qf + qrow + 4 * j);
            x2v[j] = *reinterpret_cast<const float4*>(qf + qrow + 32 + 4 * j);
            c1v[j] = *reinterpret_cast<const float4*>(cs + crow + 4 * j);
            c2v[j] = *reinterpret_cast<const float4*>(cs + crow + 32 + 4 * j);
            s1v[j] = *reinterpret_cast<const float4*>(sn + crow + 4 * j);
            s2v[j] = *reinterpret_cast<const float4*>(sn + crow + 32 + 4 * j);
        }
        // base at byte s2*32 within the row; y1 -> rel uint32 0..7,
        // y2 (elements d+32 -> bytes base+64..95) -> rel uint32 16..23
        uint32_t* qhr = reinterpret_cast<uint32_t*>(sm + SM_QH + r * FROW + s2 * 32);
        uint32_t* qlr = reinterpret_cast<uint32_t*>(sm + SM_QH + FARR + r * FROW + s2 * 32);
        #pragma unroll
        for (int j = 0; j < 4; j++) {
            const float* x1 = &x1v[j].x;
            const float* x2 = &x2v[j].x;
            const float* c1 = &c1v[j].x;
            const float* c2 = &c2v[j].x;
            const float* z1 = &s1v[j].x;
            const float* z2 = &s2v[j].x;
            float y1[4], y2[4];
            #pragma unroll
            for (int e = 0; e < 4; e++) {
                y1[e] = x1[e] * c1[e] - x2[e] * z1[e];
                y2[e] = x2[e] * c2[e] + x1[e] * z2[e];
            }
            uint32_t ph, pl;
            pack_split(y1[0], y1[1], ph, pl);
            qhr[2 * j]     = ph;  qlr[2 * j]     = pl;
            pack_split(y1[2], y1[3], ph, pl);
            qhr[2 * j + 1] = ph;  qlr[2 * j + 1] = pl;
            pack_split(y2[0], y2[1], ph, pl);
            qhr[16 + 2 * j]     = ph;  qlr[16 + 2 * j]     = pl;
            pack_split(y2[2], y2[3], ph, pl);
            qhr[16 + 2 * j + 1] = ph;  qlr[16 + 2 * j + 1] = pl;
        }
    }
    __syncthreads();

    // Q A-fragments resident
    uint32_t qfh[4][4], qfl[4][4];
    {
        const uint32_t a_row = (uint32_t)(wid * 16 + (lane & 15));
        const uint32_t a_k8  = (uint32_t)(lane >> 4);
        #pragma unroll
        for (int ks = 0; ks < 4; ks++) {
            uint32_t addr = sb + SM_QH + a_row * FROW + (ks * 2 + a_k8) * 16;
            LDSM4(qfh[ks], addr);
            LDSM4(qfl[ks], addr + FARR);
        }
    }
    __syncthreads();     // buffer-1 region free for prefetch after this

    const uint32_t kb_row = (uint32_t)((lane & 7) + ((lane >> 4) << 3));
    const uint32_t kb_k8  = (uint32_t)((lane >> 3) & 1);
    const uint32_t vb_row = (uint32_t)((lane & 7) + (((lane >> 3) & 1) << 3));
    const uint32_t vb_col = (uint32_t)((lane >> 4) << 3);

    float oacc[8][4];
    #pragma unroll
    for (int nb = 0; nb < 8; nb++)
        #pragma unroll
        for (int j = 0; j < 4; j++) oacc[nb][j] = 0.f;
    float m0 = -INFINITY, m1 = -INFINITY, l0 = 0.f, l1 = 0.f;

    int cur = 0;
    for (int kt = 0; kt <= qt; kt++) {
        if (kt + 1 <= qt) {
            flash_load_kv(sb + (uint32_t)(cur ^ 1) * KVBUF,
                          kh, kl, vh, vl, b, kt + 1, kvh, tid);
            CP_COMMIT();
            CP_WAIT1();
        } else {
            CP_WAIT0();
        }
        __syncthreads();
        const uint32_t kvb = sb + (uint32_t)cur * KVBUF;
        const bool diag = (kt == qt);

        // ---- S = Q K^T (3-term split) ----
        float sacc[8][4];
        #pragma unroll
        for (int nb = 0; nb < 8; nb++)
            #pragma unroll
            for (int j = 0; j < 4; j++) sacc[nb][j] = 0.f;

        #pragma unroll
        for (int ks = 0; ks < 4; ks++) {
            #pragma unroll
            for (int nb = 0; nb < 4; nb++) {
                if (diag && nb > wid) continue;
                uint32_t addr = kvb + OFF_KH + (kb_row + nb * 16) * FROW
                                            + (ks * 2 + kb_k8) * 16;
                uint32_t bh[4], bl[4];
                LDSM4(bh, addr);
                LDSM4(bl, addr + FARR);
                MMA_BF16(sacc[2*nb],   qfh[ks], bh);
                MMA_BF16(sacc[2*nb],   qfh[ks], bl);
                MMA_BF16(sacc[2*nb],   qfl[ks], bh);
                MMA_BF16(sacc[2*nb+1], qfh[ks], bh + 2);
                MMA_BF16(sacc[2*nb+1], qfh[ks], bl + 2);
                MMA_BF16(sacc[2*nb+1], qfl[ks], bh + 2);
            }
        }

        // ---- scale (base-2) + causal mask ----
        #pragma unroll
        for (int nb = 0; nb < 8; nb++)
            #pragma unroll
            for (int j = 0; j < 4; j++) sacc[nb][j] *= SCALE_L2E;
        if (diag) {
            #pragma unroll
            for (int nb = 0; nb < 8; nb++)
                #pragma unroll
                for (int j = 0; j < 4; j++) {
                    int n_loc = nb * 8 + 2 * (lane & 3) + (j & 1);
                    int m_loc = wid * 16 + (lane >> 2) + ((j >> 1) << 3);
                    if (n_loc > m_loc) sacc[nb][j] = -1e30f;
                }
        }

        // ---- online softmax (base-2) ----
        float mx0 = -INFINITY, mx1 = -INFINITY;
        #pragma unroll
        for (int nb = 0; nb < 8; nb++) {
            mx0 = fmaxf(mx0, fmaxf(sacc[nb][0], sacc[nb][1]));
            mx1 = fmaxf(mx1, fmaxf(sacc[nb][2], sacc[nb][3]));
        }
        mx0 = fmaxf(mx0, __shfl_xor_sync(0xffffffffu, mx0, 1));
        mx0 = fmaxf(mx0, __shfl_xor_sync(0xffffffffu, mx0, 2));
        mx1 = fmaxf(mx1, __shfl_xor_sync(0xffffffffu, mx1, 1));
        mx1 = fmaxf(mx1, __shfl_xor_sync(0xffffffffu, mx1, 2));

        float mn0 = fmaxf(m0, mx0), mn1 = fmaxf(m1, mx1);
        float al0 = exp2f(m0 - mn0), al1 = exp2f(m1 - mn1);
        m0 = mn0; m1 = mn1;

        float sum0 = 0.f, sum1 = 0.f;
        #pragma unroll
        for (int nb = 0; nb < 8; nb++) {
            sacc[nb][0] = exp2f(sacc[nb][0] - mn0);
            sacc[nb][1] = exp2f(sacc[nb][1] - mn0);
            sacc[nb][2] = exp2f(sacc[nb][2] - mn1);
            sacc[nb][3] = exp2f(sacc[nb][3] - mn1);
            sum0 += sacc[nb][0] + sacc[nb][1];
            sum1 += sacc[nb][2] + sacc[nb][3];
        }
        sum0 += __shfl_xor_sync(0xffffffffu, sum0, 1);
        sum0 += __shfl_xor_sync(0xffffffffu, sum0, 2);
        sum1 += __shfl_xor_sync(0xffffffffu, sum1, 1);
        sum1 += __shfl_xor_sync(0xffffffffu, sum1, 2);
        l0 = l0 * al0 + sum0;
        l1 = l1 * al1 + sum1;

        #pragma unroll
        for (int nb = 0; nb < 8; nb++) {
            oacc[nb][0] *= al0; oacc[nb][1] *= al0;
            oacc[nb][2] *= al1; oacc[nb][3] *= al1;
        }

        // ---- streamed pack + PV ----
        #pragma unroll
        for (int j16 = 0; j16 < 4; j16++) {
            if (diag && j16 > wid) continue;
            uint32_t pfh[4], pfl[4];
            {
                float* c0 = sacc[2*j16];
                float* c1 = sacc[2*j16 + 1];
                #pragma unroll
                for (int a = 0; a < 4; a++) {
                    float v0 = (a < 2) ? c0[(a & 1) * 2]     : c1[(a & 1) * 2];
                    float v1 = (a < 2) ? c0[(a & 1) * 2 + 1] : c1[(a & 1) * 2 + 1];
                    pack_split(v0, v1, pfh[a], pfl[a]);
                }
            }
            #pragma unroll
            for (int nb = 0; nb < 4; nb++) {
                uint32_t addr = kvb + OFF_VH
                              + (j16 * 16 + vb_row) * FROW
                              + (nb * 16 + vb_col) * 2;
                uint32_t vhf[4], vlf[4];
                LDSM4T(vhf, addr);
                LDSM4T(vlf, addr + FARR);
                MMA_BF16(oacc[2*nb],   pfh, vhf);
                MMA_BF16(oacc[2*nb],   pfh, vlf);
                MMA_BF16(oacc[2*nb],   pfl, vhf);
                MMA_BF16(oacc[2*nb+1], pfh, vhf + 2);
                MMA_BF16(oacc[2*nb+1], pfh, vlf + 2);
                MMA_BF16(oacc[2*nb+1], pfl, vhf + 2);
            }
        }

        __syncthreads();
        cur ^= 1;
    }

    // ---- epilogue: normalize, split to bf16 hi/lo, store directly ----
    float inv0 = 1.f / l0, inv1 = 1.f / l1;
    size_t row0 = (size_t)(b * TT + qt * 64 + wid * 16 + (lane >> 2));
    #pragma unroll
    for (int nb = 0; nb < 8; nb++) {
        size_t col = (size_t)(h * 64 + nb * 8 + 2 * (lane & 3));
        uint32_t ph, pl;
        pack_split(oacc[nb][0] * inv0, oacc[nb][1] * inv0, ph, pl);
        *reinterpret_cast<uint32_t*>(&yh[row0 * EE + col]) = ph;
        *reinterpret_cast<uint32_t*>(&yl[row0 * EE + col]) = pl;
        pack_split(oacc[nb][2] * inv1, oacc[nb][3] * inv1, ph, pl);
        *reinterpret_cast<uint32_t*>(&yh[(row0 + 8) * EE + col]) = ph;
        *reinterpret_cast<uint32_t*>(&yl[(row0 + 8) * EE + col]) = pl;
    }
}

// ---------------------------------------------------------------------------
// kernel_launch — 5 launches; flash_mma is #4 (profiler window)
// ---------------------------------------------------------------------------
extern "C" void kernel_launch(void* const* d_in, const int* in_sizes, int n_in,
                              void* d_out, int out_size)
{
    const float* x   = (const float*)d_in[0];
    const float* cs  = (const float*)d_in[1];
    const float* sn  = (const float*)d_in[2];
    const float* Wq  = (const float*)d_in[3];
    const float* Wk  = (const float*)d_in[4];
    const float* Wv  = (const float*)d_in[5];
    const float* Wo  = (const float*)d_in[6];
    float* out = (float*)d_out;

    float *q, *k;
    cudaGetSymbolAddress((void**)&q, g_q);
    cudaGetSymbolAddress((void**)&k, g_k);

    __nv_bfloat16 *xh, *xl, *yh, *yl;
    __nv_bfloat16 *wqh, *wql, *wkh, *wkl, *wvh, *wvl, *woh, *wol;
    __nv_bfloat16 *khp, *klp, *vhp, *vlp;
    cudaGetSymbolAddress((void**)&xh,  g_x_hi);  cudaGetSymbolAddress((void**)&xl,  g_x_lo);
    cudaGetSymbolAddress((void**)&yh,  g_y_hi);  cudaGetSymbolAddress((void**)&yl,  g_y_lo);
    cudaGetSymbolAddress((void**)&wqh, g_wq_hi); cudaGetSymbolAddress((void**)&wql, g_wq_lo);
    cudaGetSymbolAddress((void**)&wkh, g_wk_hi); cudaGetSymbolAddress((void**)&wkl, g_wk_lo);
    cudaGetSymbolAddress((void**)&wvh, g_wv_hi); cudaGetSymbolAddress((void**)&wvl, g_wv_lo);
    cudaGetSymbolAddress((void**)&woh, g_wo_hi); cudaGetSymbolAddress((void**)&wol, g_wo_lo);
    cudaGetSymbolAddress((void**)&khp, g_kh);    cudaGetSymbolAddress((void**)&klp, g_kl);
    cudaGetSymbolAddress((void**)&vhp, g_vh);    cudaGetSymbolAddress((void**)&vlp, g_vl);

    cudaFuncSetAttribute(gemm_mma, cudaFuncAttributeMaxDynamicSharedMemorySize,
                         GEMM_SMEM);
    cudaFuncSetAttribute(gemm_mma_qkv, cudaFuncAttributeMaxDynamicSharedMemorySize,
                         GEMM_SMEM);
    cudaFuncSetAttribute(flash_mma, cudaFuncAttributeMaxDynamicSharedMemorySize,
                         FLASH_SMEM);

    // #1: all input splits
    {
        SplitArgs a;
        a.in[0] = x;  a.hi[0] = xh;  a.lo[0] = xl;  a.n4[0] = MM * EE / 4;
        a.in[1] = Wq; a.hi[1] = wqh; a.lo[1] = wql; a.n4[1] = EE * EE / 4;
        a.in[2] = Wk; a.hi[2] = wkh; a.lo[2] = wkl; a.n4[2] = KVH * HD * EE / 4;
        a.in[3] = Wv; a.hi[3] = wvh; a.lo[3] = wvl; a.n4[3] = KVH * HD * EE / 4;
        a.in[4] = Wo; a.hi[4] = woh; a.lo[4] = wol; a.n4[4] = EE * EE / 4;
        int maxb = (MM * EE / 4 + 255) / 256;
        split_all<<<dim3(maxb, 5), 256>>>(a);
    }

    // #2: Q + K + V projections (V emits bf16 hi/lo directly)
    gemm_mma_qkv<<<dim3(12, MM / 128), 256, GEMM_SMEM>>>(
        xh, xl, wqh, wql, wkh, wkl, wvh, wvl, q, k, vhp, vlp);

    // #3: k rope + split
    {
        int n = BB * TT * KVH * 32;
        rope_k<<<(n + 255) / 256, 256>>>(k, cs, sn, khp, klp);
    }

    // #4: flash attention (q rope fused; writes yh/yl) — profiler window
    flash_mma<<<dim3(TT / 64, HH, BB), 128, FLASH_SMEM>>>(
        q, cs, sn, khp, klp, vhp, vlp, yh, yl);

    // #5: output projection
    gemm_mma<<<dim3(EE / 128, MM / 128), 256, GEMM_SMEM>>>(yh, yl, woh, wol, out, MM, EE, EE);
}